// round 13
// baseline (speedup 1.0000x reference)
#include <cuda_runtime.h>
#include <cuda_bf16.h>
#include <cuda_fp16.h>
#include <cstdint>

#define NV 8192
#define DV 32
#define TV 12
#define RV 192   /* B*C*T = 2*8*12 */

// ---------------- device scratch (no cudaMalloc anywhere) ----------------
__device__ float    g_core[DV * DV];
__device__ float    g_aT[DV * NV];                    // a transposed [f][n]
__device__ __nv_bfloat16 g_A2h[NV * DV];              // nv2 hi bf16 [m][k]
__device__ __nv_bfloat16 g_A2l[NV * DV];              // nv2 lo
__device__ __nv_bfloat16 g_aTh[DV * NV];              // aT hi bf16 [k][n]
__device__ __nv_bfloat16 g_aTl[DV * NV];              // aT lo
__device__ uint32_t g_Bh32[NV * 96];                  // xs fp16 pairs [n][r] (x4096)
__device__ float    g_cspart[64 * NV];                // column-sum partials per m-block
__device__ float    g_rinv[NV];                       // 4096/rowsum

// ---------------- mma / ldmatrix / cp.async helpers (plain sm_80+ PTX) ----------------
__device__ __forceinline__ uint32_t smem_u32(const void* p) {
    uint32_t a;
    asm("{ .reg .u64 t; cvta.to.shared.u64 t, %1; cvt.u32.u64 %0, t; }" : "=r"(a) : "l"(p));
    return a;
}
__device__ __forceinline__ void ldsm_x4(uint32_t &r0, uint32_t &r1, uint32_t &r2, uint32_t &r3,
                                        uint32_t a) {
    asm volatile("ldmatrix.sync.aligned.m8n8.x4.shared.b16 {%0,%1,%2,%3}, [%4];"
                 : "=r"(r0), "=r"(r1), "=r"(r2), "=r"(r3) : "r"(a));
}
__device__ __forceinline__ void ldsm_x4t(uint32_t &r0, uint32_t &r1, uint32_t &r2, uint32_t &r3,
                                         uint32_t a) {
    asm volatile("ldmatrix.sync.aligned.m8n8.x4.trans.shared.b16 {%0,%1,%2,%3}, [%4];"
                 : "=r"(r0), "=r"(r1), "=r"(r2), "=r"(r3) : "r"(a));
}
__device__ __forceinline__ void ldsm_x2t(uint32_t &r0, uint32_t &r1, uint32_t a) {
    asm volatile("ldmatrix.sync.aligned.m8n8.x2.trans.shared.b16 {%0,%1}, [%2];"
                 : "=r"(r0), "=r"(r1) : "r"(a));
}
__device__ __forceinline__ void mma16816(float* c, uint32_t a0, uint32_t a1, uint32_t a2,
                                         uint32_t a3, uint32_t b0, uint32_t b1) {
    asm volatile(
        "mma.sync.aligned.m16n8k16.row.col.f32.bf16.bf16.f32 "
        "{%0,%1,%2,%3}, {%4,%5,%6,%7}, {%8,%9}, {%0,%1,%2,%3};"
        : "+f"(c[0]), "+f"(c[1]), "+f"(c[2]), "+f"(c[3])
        : "r"(a0), "r"(a1), "r"(a2), "r"(a3), "r"(b0), "r"(b1));
}
__device__ __forceinline__ void mma16816h(float* c, uint32_t a0, uint32_t a1, uint32_t a2,
                                          uint32_t a3, uint32_t b0, uint32_t b1) {
    asm volatile(
        "mma.sync.aligned.m16n8k16.row.col.f32.f16.f16.f32 "
        "{%0,%1,%2,%3}, {%4,%5,%6,%7}, {%8,%9}, {%0,%1,%2,%3};"
        : "+f"(c[0]), "+f"(c[1]), "+f"(c[2]), "+f"(c[3])
        : "r"(a0), "r"(a1), "r"(a2), "r"(a3), "r"(b0), "r"(b1));
}
__device__ __forceinline__ void cp16(uint32_t d, const void* s) {
    asm volatile("cp.async.cg.shared.global [%0], [%1], 16;" :: "r"(d), "l"(s) : "memory");
}

// ========== K1a: core[e][f] = sum_d tv[d]*k[d][e][f] ==========
__global__ void k_core(const float* __restrict__ timevec, const float* __restrict__ kk,
                       const int* __restrict__ tind) {
    int e = threadIdx.x >> 5, f = threadIdx.x & 31;
    int ti = tind[0];
    float s = 0.f;
#pragma unroll
    for (int d = 0; d < DV; ++d) s += timevec[ti * DV + d] * kk[(d * DV + e) * DV + f];
    g_core[e * DV + f] = s;
}

// ========== K1b: aT[f][n] = sum_e nv1[n][e]*core[e][f] ==========
__global__ void k_amat(const float* __restrict__ nv1) {
    __shared__ float sc[DV * DV];
    int tid = threadIdx.x;
    for (int i = tid; i < DV * DV; i += 256) sc[i] = g_core[i];
    __syncthreads();
    int n = blockIdx.x * 8 + (tid >> 5);
    int f = tid & 31;
    float s = 0.f;
#pragma unroll
    for (int e = 0; e < DV; ++e) s += nv1[n * DV + e] * sc[e * DV + f];
    g_aT[f * NV + n] = s;
}

// ========== K1c: bf16 hi/lo pre-split of nv2 and aT (logit GEMM operands) ==========
__global__ void k_split(const float* __restrict__ nv2) {
    int idx = blockIdx.x * 256 + threadIdx.x;
    if (idx < NV * DV) {
        float v = nv2[idx];
        __nv_bfloat16 h = __float2bfloat16_rn(v);
        g_A2h[idx] = h;
        g_A2l[idx] = __float2bfloat16_rn(v - __bfloat162float(h));
    } else {
        int j = idx - NV * DV;
        float v = g_aT[j];
        __nv_bfloat16 h = __float2bfloat16_rn(v);
        g_aTh[j] = h;
        g_aTl[j] = __float2bfloat16_rn(v - __bfloat162float(h));
    }
}

// ========== K2: colsum pass — 3-product logit mma + exp + colsum ==========
// grid (64 nblk, 64 mblk), CTA 128m x 128n, 256 thr = 8 warps (wm 2 x wn 4).
// smem: A2h 16K | A2l 16K | aTh 8704 | aTl 8704 = 50176
#define CS_AL 16384
#define CS_BH 32768
#define CS_BL 41472

__global__ __launch_bounds__(256) void k_colsum() {
    __shared__ char sm[50176];
    uint32_t sb = smem_u32(sm);
    const int tid = threadIdx.x, lane = tid & 31, wid = tid >> 5;
    const int wm = wid & 1, wn = wid >> 1;
    const int n0 = blockIdx.x * 128;
    const int i0 = blockIdx.y * 128;

#pragma unroll
    for (int l = 0; l < 4; ++l) {
        int idx = tid + l * 256;                 // 1024 = 2 halves x 128 rows x 4 chunks
        int half = idx >> 9, j = idx & 511;
        int r = j >> 2, kb = j & 3;
        const char* src = (const char*)(half ? g_A2l : g_A2h) + (size_t)(i0 + r) * 64 + kb * 16;
        cp16(sb + half * CS_AL + r * 128 + ((uint32_t)((kb ^ (r & 3)) | (r & 4)) << 4), src);
    }
#pragma unroll
    for (int l = 0; l < 4; ++l) {
        int idx = tid + l * 256;                 // 1024 = 2 halves x 32 rows x 16 chunks
        int half = idx >> 9, j = idx & 511;
        int kr = j >> 4, cb = j & 15;
        const char* src = (const char*)(half ? g_aTl : g_aTh) + ((size_t)kr * NV + n0) * 2 + cb * 16;
        cp16(sb + (half ? CS_BL : CS_BH) + kr * 272 + cb * 16, src);
    }
    asm volatile("cp.async.commit_group;" ::: "memory");
    asm volatile("cp.async.wait_group 0;" ::: "memory");
    __syncthreads();

    float acc[4][4][4];
#pragma unroll
    for (int mt = 0; mt < 4; ++mt)
#pragma unroll
        for (int nt = 0; nt < 4; ++nt)
#pragma unroll
            for (int q = 0; q < 4; ++q) acc[mt][nt][q] = 0.f;

#pragma unroll
    for (int ks = 0; ks < 2; ++ks) {
        uint32_t bh[4][2], bl[4][2];
        int krow = ks * 16 + (lane & 15);
#pragma unroll
        for (int nt = 0; nt < 4; ++nt) {
            uint32_t ba = sb + CS_BH + krow * 272 + (wn * 32 + nt * 8) * 2;
            ldsm_x2t(bh[nt][0], bh[nt][1], ba);
            ldsm_x2t(bl[nt][0], bl[nt][1], ba + (CS_BL - CS_BH));
        }
        int kb = ks * 2 + (lane >> 4);
#pragma unroll
        for (int mt = 0; mt < 4; ++mt) {
            int rr = wm * 64 + mt * 16 + (lane & 15);
            uint32_t slot = (uint32_t)((kb ^ (rr & 3)) | (rr & 4));
            uint32_t aa = sb + rr * 128 + (slot << 4);
            uint32_t ah0, ah1, ah2, ah3, al0, al1, al2, al3;
            ldsm_x4(ah0, ah1, ah2, ah3, aa);
            ldsm_x4(al0, al1, al2, al3, aa + CS_AL);
#pragma unroll
            for (int nt = 0; nt < 4; ++nt) {
                mma16816(acc[mt][nt], ah0, ah1, ah2, ah3, bh[nt][0], bh[nt][1]);
                mma16816(acc[mt][nt], ah0, ah1, ah2, ah3, bl[nt][0], bl[nt][1]);
                mma16816(acc[mt][nt], al0, al1, al2, al3, bh[nt][0], bh[nt][1]);
            }
        }
    }
    __syncthreads();   // operands dead; reuse region for red

    float* red = (float*)sm;
    int slot = wm * 8 + (lane >> 2);
#pragma unroll
    for (int nt = 0; nt < 4; ++nt) {
        float se = 0.f, so = 0.f;
#pragma unroll
        for (int mt = 0; mt < 4; ++mt) {
            float* c = acc[mt][nt];
            se += __expf(fmaxf(c[0], 0.f)) + __expf(fmaxf(c[2], 0.f));
            so += __expf(fmaxf(c[1], 0.f)) + __expf(fmaxf(c[3], 0.f));
        }
        *(float2*)&red[slot * 132 + wn * 32 + nt * 8 + (lane & 3) * 2] = make_float2(se, so);
    }
    __syncthreads();
    if (tid < 128) {
        float s = 0.f;
#pragma unroll
        for (int q = 0; q < 16; ++q) s += red[q * 132 + tid];
        g_cspart[blockIdx.y * NV + n0 + tid] = s;
    }
}

// ========== K2b: rowsum reduce -> 4096/rowsum ==========
__global__ void k_rsum() {
    int n = blockIdx.x * 64 + threadIdx.x;
    float s = 0.f;
#pragma unroll
    for (int mb = 0; mb < 64; ++mb) s += g_cspart[mb * NV + n];
    g_rinv[n] = 4096.0f / s;
}

// ========== K3: B[n][r] = x[bc][n][t] * (4096/rowsum[n]) as fp16 (coalesced) ==========
__global__ __launch_bounds__(256) void k_xs(const float* __restrict__ x) {
    __shared__ float sx[32 * 193];
    __shared__ float sinv[32];
    int tid = threadIdx.x;
    int n0 = blockIdx.x * 32;
    if (tid < 32) sinv[tid] = g_rinv[n0 + tid];
#pragma unroll
    for (int bc = 0; bc < 16; ++bc) {
        const float* src = x + ((size_t)bc * NV + n0) * TV;
        for (int i = tid; i < 32 * TV; i += 256) {
            int nl = i / TV, t = i - nl * TV;
            sx[nl * 193 + bc * TV + t] = src[i];
        }
    }
    __syncthreads();
#pragma unroll
    for (int it = 0; it < 12; ++it) {
        int idx = tid + it * 256;
        int nl = idx / 96, rp = idx - nl * 96;
        float inv = sinv[nl];
        __half2 hh = __floats2half2_rn(sx[nl * 193 + 2 * rp] * inv,
                                       sx[nl * 193 + 2 * rp + 1] * inv);
        g_Bh32[(n0 + nl) * 96 + rp] = *(uint32_t*)&hh;
    }
}

// ========== K4: FUSED  out[m][r] = sum_n exp(relu(logit[m][n])) * xs[n][r] ==========
// 128 CTAs x 64 m-rows, 256 thr = 8 warps (2m x 4n). n swept in 64 chunks of 128.
// smem: A2 hi/lo 16KB | aT chunk hi/lo db 2x17408 | P stage 16KB | xs chunk db 2x51200
#define F_AT 16384
#define F_P  51200
#define F_B  67584
#define F_SMEM 169984

__device__ __forceinline__ void f_load(uint32_t sb, int buf, int nc, int tid) {
    uint32_t SAT = sb + F_AT + buf * 17408;
#pragma unroll
    for (int l = 0; l < 4; ++l) {
        int idx = tid + l * 256;                 // 1024 = 2 halves x 32 rows x 16 chunks
        int half = idx >> 9, j = idx & 511;
        int kr = j >> 4, cb = j & 15;
        const char* src = (const char*)(half ? g_aTl : g_aTh) + ((size_t)kr * NV + nc) * 2 + cb * 16;
        cp16(SAT + half * 8704 + kr * 272 + cb * 16, src);
    }
    uint32_t SB = sb + F_B + buf * 51200;
    const char* bh = (const char*)g_Bh32;
#pragma unroll
    for (int l = 0; l < 12; ++l) {
        int idx = tid + l * 256;                 // 3072 = 128 rows x 24 chunks
        int kr = idx / 24, cb = idx - kr * 24;
        cp16(SB + kr * 400 + cb * 16, bh + (size_t)(nc + kr) * 384 + cb * 16);
    }
}

__global__ __launch_bounds__(256) void k_fused(float* __restrict__ out) {
    extern __shared__ char sm[];
    uint32_t sb = smem_u32(sm);
    const int tid = threadIdx.x, lane = tid & 31, wid = tid >> 5;
    const int wm = wid & 1, wn = wid >> 1;       // wn 0..3
    const int i0 = blockIdx.x * 64;

    // A2 hi/lo for our 64 m rows (resident all kernel)
#pragma unroll
    for (int l = 0; l < 2; ++l) {
        int idx = tid + l * 256;                 // 512 = 2 halves x 64 rows x 4 chunks
        int half = idx >> 8, j = idx & 255;
        int r = j >> 2, kb = j & 3;
        const char* src = (const char*)(half ? g_A2l : g_A2h) + (size_t)(i0 + r) * 64 + kb * 16;
        cp16(sb + half * 8192 + r * 128 + ((uint32_t)((kb ^ (r & 3)) | (r & 4)) << 4), src);
    }
    f_load(sb, 0, 0, tid);
    asm volatile("cp.async.commit_group;" ::: "memory");

    float acc[2][6][4];
#pragma unroll
    for (int mt = 0; mt < 2; ++mt)
#pragma unroll
        for (int nt = 0; nt < 6; ++nt)
#pragma unroll
            for (int q = 0; q < 4; ++q) acc[mt][nt][q] = 0.f;

    for (int c = 0; c < 64; ++c) {
        int buf = c & 1;
        if (c + 1 < 64) f_load(sb, buf ^ 1, (c + 1) * 128, tid);
        asm volatile("cp.async.commit_group;" ::: "memory");
        asm volatile("cp.async.wait_group 1;" ::: "memory");
        __syncthreads();

        // ---- logit mma (3-product bf16) over this 64m x 128n chunk ----
        float lg[2][4][4];
#pragma unroll
        for (int mt = 0; mt < 2; ++mt)
#pragma unroll
            for (int nt = 0; nt < 4; ++nt)
#pragma unroll
                for (int q = 0; q < 4; ++q) lg[mt][nt][q] = 0.f;

        uint32_t SAT = sb + F_AT + buf * 17408;
#pragma unroll
        for (int ks = 0; ks < 2; ++ks) {
            uint32_t bh[4][2], bl[4][2];
            int krow = ks * 16 + (lane & 15);
#pragma unroll
            for (int nt = 0; nt < 4; ++nt) {
                uint32_t ba = SAT + krow * 272 + (wn * 32 + nt * 8) * 2;
                ldsm_x2t(bh[nt][0], bh[nt][1], ba);
                ldsm_x2t(bl[nt][0], bl[nt][1], ba + 8704);
            }
            int kb = ks * 2 + (lane >> 4);
#pragma unroll
            for (int mt = 0; mt < 2; ++mt) {
                int rr = wm * 32 + mt * 16 + (lane & 15);
                uint32_t slot = (uint32_t)((kb ^ (rr & 3)) | (rr & 4));
                uint32_t aa = sb + rr * 128 + (slot << 4);
                uint32_t ah0, ah1, ah2, ah3, al0, al1, al2, al3;
                ldsm_x4(ah0, ah1, ah2, ah3, aa);
                ldsm_x4(al0, al1, al2, al3, aa + 8192);
#pragma unroll
                for (int nt = 0; nt < 4; ++nt) {
                    mma16816(lg[mt][nt], ah0, ah1, ah2, ah3, bh[nt][0], bh[nt][1]);
                    mma16816(lg[mt][nt], ah0, ah1, ah2, ah3, bl[nt][0], bl[nt][1]);
                    mma16816(lg[mt][nt], al0, al1, al2, al3, bh[nt][0], bh[nt][1]);
                }
            }
        }

        // ---- exp + fp16 stage into swizzled P tile ----
#pragma unroll
        for (int mt = 0; mt < 2; ++mt) {
            int mlo = wm * 32 + mt * 16 + (lane >> 2);
            int mhi = mlo + 8;
#pragma unroll
            for (int nt = 0; nt < 4; ++nt) {
                float* cc = lg[mt][nt];
                int n = wn * 32 + nt * 8 + (lane & 3) * 2;
                __half2 h01 = __floats2half2_rn(__expf(fmaxf(cc[0], 0.f)),
                                                __expf(fmaxf(cc[1], 0.f)));
                __half2 h23 = __floats2half2_rn(__expf(fmaxf(cc[2], 0.f)),
                                                __expf(fmaxf(cc[3], 0.f)));
                int half = n >> 6, kb16 = (n & 63) >> 3, wo = (n & 7) >> 1;
                uint32_t a0 = (uint32_t)(F_P + half * 8192 + mlo * 128 +
                              (((uint32_t)(kb16 ^ (mlo & 7))) << 4) + wo * 4);
                uint32_t a1 = (uint32_t)(F_P + half * 8192 + mhi * 128 +
                              (((uint32_t)(kb16 ^ (mhi & 7))) << 4) + wo * 4);
                *(uint32_t*)(sm + a0) = *(uint32_t*)&h01;
                *(uint32_t*)(sm + a1) = *(uint32_t*)&h23;
            }
        }
        __syncthreads();

        // ---- main fp16 mma: acc += P_tile[64m x 128k] * xs[128k x 192r] ----
        uint32_t SB = sb + F_B + buf * 51200;
#pragma unroll
        for (int ks = 0; ks < 8; ++ks) {
            uint32_t bm[3][4];
            int krow = ks * 16 + (lane & 15);
#pragma unroll
            for (int j = 0; j < 3; ++j) {
                uint32_t ba = SB + krow * 400 + (wn * 48 + j * 16 + (lane >> 4) * 8) * 2;
                ldsm_x4t(bm[j][0], bm[j][1], bm[j][2], bm[j][3], ba);
            }
            int half = ks >> 2;
            int kb = (ks & 3) * 2 + (lane >> 4);
#pragma unroll
            for (int mt = 0; mt < 2; ++mt) {
                int rr = wm * 32 + mt * 16 + (lane & 15);
                uint32_t aa = sb + F_P + half * 8192 + rr * 128 +
                              (((uint32_t)(kb ^ (rr & 7))) << 4);
                uint32_t a0, a1, a2, a3;
                ldsm_x4(a0, a1, a2, a3, aa);
#pragma unroll
                for (int nt = 0; nt < 6; ++nt)
                    mma16816h(acc[mt][nt], a0, a1, a2, a3,
                              bm[nt >> 1][2 * (nt & 1)], bm[nt >> 1][2 * (nt & 1) + 1]);
            }
        }
        __syncthreads();   // protect sP/sAT before next chunk's stage/loads
    }

    // ---- direct output (undo 4096 scale); r,r+1 share bc (t even) ----
    const float scv = 1.0f / 4096.0f;
#pragma unroll
    for (int mt = 0; mt < 2; ++mt) {
#pragma unroll
        for (int nt = 0; nt < 6; ++nt) {
            int m = i0 + wm * 32 + mt * 16 + (lane >> 2);
            int r = wn * 48 + nt * 8 + (lane & 3) * 2;
            int bc = r / TV, t = r - bc * TV;
            float* o = out + ((size_t)bc * NV + m) * TV + t;
            o[0] = acc[mt][nt][0] * scv;
            o[1] = acc[mt][nt][1] * scv;
            float* o2 = out + ((size_t)bc * NV + m + 8) * TV + t;
            o2[0] = acc[mt][nt][2] * scv;
            o2[1] = acc[mt][nt][3] * scv;
        }
    }
}

extern "C" void kernel_launch(void* const* d_in, const int* in_sizes, int n_in,
                              void* d_out, int out_size) {
    const float* x    = (const float*)d_in[0];
    const float* nv1  = (const float*)d_in[1];
    const float* nv2  = (const float*)d_in[2];
    const float* tvv  = (const float*)d_in[3];
    const float* kk   = (const float*)d_in[4];
    const int*   tind = (const int*)d_in[5];
    float* out = (float*)d_out;

    cudaFuncSetAttribute(k_fused, cudaFuncAttributeMaxDynamicSharedMemorySize, F_SMEM);

    k_core<<<1, 1024>>>(tvv, kk, tind);
    k_amat<<<NV / 8, 256>>>(nv1);
    k_split<<<2 * NV * DV / 256, 256>>>(nv2);
    k_colsum<<<dim3(64, 64), 256>>>();
    k_rsum<<<NV / 64, 64>>>();
    k_xs<<<NV / 32, 256>>>(x);
    k_fused<<<128, 256, F_SMEM>>>(out);
}

// round 14
// speedup vs baseline: 1.7488x; 1.7488x over previous
#include <cuda_runtime.h>
#include <cuda_bf16.h>
#include <cuda_fp16.h>
#include <cstdint>

#define NV 8192
#define DV 32
#define TV 12
#define RV 192   /* B*C*T = 2*8*12 */

// ---------------- device scratch (no cudaMalloc anywhere) ----------------
__device__ float    g_core[DV * DV];
__device__ float    g_aT[DV * NV];                    // a transposed [f][n]
__device__ __nv_bfloat16 g_A2h[NV * DV];              // nv2 hi bf16 [m][k]
__device__ __nv_bfloat16 g_A2l[NV * DV];              // nv2 lo
__device__ __nv_bfloat16 g_aTh[DV * NV];              // aT hi bf16 [k][n]
__device__ __nv_bfloat16 g_aTl[DV * NV];              // aT lo
__device__ uint32_t g_Ph32[(size_t)NV * NV / 2];      // Pt fp16 pairs [m][n], 128MB
__device__ uint32_t g_Bh32[NV * 96];                  // xs fp16 pairs [n][r] (x4096)
__device__ float    g_cspart[64 * NV];                // column-sum partials per m-block
__device__ float    g_rinv[NV];                       // 4096/rowsum
__device__ float    g_part2[2ULL * NV * RV];          // split-k partials fp32

// ---------------- mma / ldmatrix / cp.async helpers (plain sm_80+ PTX) ----------------
__device__ __forceinline__ uint32_t smem_u32(const void* p) {
    uint32_t a;
    asm("{ .reg .u64 t; cvta.to.shared.u64 t, %1; cvt.u32.u64 %0, t; }" : "=r"(a) : "l"(p));
    return a;
}
__device__ __forceinline__ void ldsm_x4(uint32_t &r0, uint32_t &r1, uint32_t &r2, uint32_t &r3,
                                        uint32_t a) {
    asm volatile("ldmatrix.sync.aligned.m8n8.x4.shared.b16 {%0,%1,%2,%3}, [%4];"
                 : "=r"(r0), "=r"(r1), "=r"(r2), "=r"(r3) : "r"(a));
}
__device__ __forceinline__ void ldsm_x4t(uint32_t &r0, uint32_t &r1, uint32_t &r2, uint32_t &r3,
                                         uint32_t a) {
    asm volatile("ldmatrix.sync.aligned.m8n8.x4.trans.shared.b16 {%0,%1,%2,%3}, [%4];"
                 : "=r"(r0), "=r"(r1), "=r"(r2), "=r"(r3) : "r"(a));
}
__device__ __forceinline__ void ldsm_x2t(uint32_t &r0, uint32_t &r1, uint32_t a) {
    asm volatile("ldmatrix.sync.aligned.m8n8.x2.trans.shared.b16 {%0,%1}, [%2];"
                 : "=r"(r0), "=r"(r1) : "r"(a));
}
__device__ __forceinline__ void mma16816(float* c, uint32_t a0, uint32_t a1, uint32_t a2,
                                         uint32_t a3, uint32_t b0, uint32_t b1) {
    asm volatile(
        "mma.sync.aligned.m16n8k16.row.col.f32.bf16.bf16.f32 "
        "{%0,%1,%2,%3}, {%4,%5,%6,%7}, {%8,%9}, {%0,%1,%2,%3};"
        : "+f"(c[0]), "+f"(c[1]), "+f"(c[2]), "+f"(c[3])
        : "r"(a0), "r"(a1), "r"(a2), "r"(a3), "r"(b0), "r"(b1));
}
__device__ __forceinline__ void mma16816h(float* c, uint32_t a0, uint32_t a1, uint32_t a2,
                                          uint32_t a3, uint32_t b0, uint32_t b1) {
    asm volatile(
        "mma.sync.aligned.m16n8k16.row.col.f32.f16.f16.f32 "
        "{%0,%1,%2,%3}, {%4,%5,%6,%7}, {%8,%9}, {%0,%1,%2,%3};"
        : "+f"(c[0]), "+f"(c[1]), "+f"(c[2]), "+f"(c[3])
        : "r"(a0), "r"(a1), "r"(a2), "r"(a3), "r"(b0), "r"(b1));
}
__device__ __forceinline__ void cp16(uint32_t d, const void* s) {
    asm volatile("cp.async.cg.shared.global [%0], [%1], 16;" :: "r"(d), "l"(s) : "memory");
}

// ========== K1a: core[e][f] = sum_d tv[d]*k[d][e][f] ==========
__global__ void k_core(const float* __restrict__ timevec, const float* __restrict__ kk,
                       const int* __restrict__ tind) {
    int e = threadIdx.x >> 5, f = threadIdx.x & 31;
    int ti = tind[0];
    float s = 0.f;
#pragma unroll
    for (int d = 0; d < DV; ++d) s += timevec[ti * DV + d] * kk[(d * DV + e) * DV + f];
    g_core[e * DV + f] = s;
}

// ========== K1b: aT[f][n] = sum_e nv1[n][e]*core[e][f] ==========
__global__ void k_amat(const float* __restrict__ nv1) {
    __shared__ float sc[DV * DV];
    int tid = threadIdx.x;
    for (int i = tid; i < DV * DV; i += 256) sc[i] = g_core[i];
    __syncthreads();
    int n = blockIdx.x * 8 + (tid >> 5);
    int f = tid & 31;
    float s = 0.f;
#pragma unroll
    for (int e = 0; e < DV; ++e) s += nv1[n * DV + e] * sc[e * DV + f];
    g_aT[f * NV + n] = s;
}

// ========== K1c: bf16 hi/lo pre-split of nv2 and aT (logit GEMM operands) ==========
__global__ void k_split(const float* __restrict__ nv2) {
    int idx = blockIdx.x * 256 + threadIdx.x;
    if (idx < NV * DV) {
        float v = nv2[idx];
        __nv_bfloat16 h = __float2bfloat16_rn(v);
        g_A2h[idx] = h;
        g_A2l[idx] = __float2bfloat16_rn(v - __bfloat162float(h));
    } else {
        int j = idx - NV * DV;
        float v = g_aT[j];
        __nv_bfloat16 h = __float2bfloat16_rn(v);
        g_aTh[j] = h;
        g_aTl[j] = __float2bfloat16_rn(v - __bfloat162float(h));
    }
}

// ========== K2: HMMA logit GEMM + exp + fp16 store + colsum ==========
// grid (64 nblk, 64 mblk), CTA 128m x 128n, 256 thr = 8 warps (wm 2 x wn 4).
#define PJ_AH 0
#define PJ_AL 16384
#define PJ_BH 32768
#define PJ_BL 41472
#define PJ_RED 34816          /* after fp16 stage (reuses operand region) */
#define PJ_SMEM 50176

__global__ __launch_bounds__(256) void k_padj_mma() {
    extern __shared__ char sm[];
    uint32_t sb = smem_u32(sm);
    const int tid = threadIdx.x, lane = tid & 31, wid = tid >> 5;
    const int wm = wid & 1;
    const int wn = wid >> 1;
    const int n0 = blockIdx.x * 128;
    const int i0 = blockIdx.y * 128;

#pragma unroll
    for (int l = 0; l < 4; ++l) {
        int idx = tid + l * 256;
        int half = idx >> 9, j = idx & 511;
        int r = j >> 2, kb = j & 3;
        const __nv_bfloat16* src = (half ? g_A2l : g_A2h) + (size_t)(i0 + r) * DV + kb * 8;
        uint32_t slot = (uint32_t)((kb ^ (r & 3)) | (r & 4));
        cp16(sb + (half ? PJ_AL : PJ_AH) + r * 128 + slot * 16, src);
    }
#pragma unroll
    for (int l = 0; l < 4; ++l) {
        int idx = tid + l * 256;
        int half = idx >> 9, j = idx & 511;
        int kr = j >> 4, cb = j & 15;
        const __nv_bfloat16* src = (half ? g_aTl : g_aTh) + (size_t)kr * NV + n0 + cb * 8;
        cp16(sb + (half ? PJ_BL : PJ_BH) + kr * 272 + cb * 16, src);
    }
    asm volatile("cp.async.commit_group;" ::: "memory");
    asm volatile("cp.async.wait_group 0;" ::: "memory");
    __syncthreads();

    float acc[4][4][4];
#pragma unroll
    for (int mt = 0; mt < 4; ++mt)
#pragma unroll
        for (int nt = 0; nt < 4; ++nt)
#pragma unroll
            for (int q = 0; q < 4; ++q) acc[mt][nt][q] = 0.f;

#pragma unroll
    for (int ks = 0; ks < 2; ++ks) {
        uint32_t bh[4][2], bl[4][2];
        int krow = ks * 16 + (lane & 15);
#pragma unroll
        for (int nt = 0; nt < 4; ++nt) {
            uint32_t ba = sb + PJ_BH + krow * 272 + (wn * 32 + nt * 8) * 2;
            ldsm_x2t(bh[nt][0], bh[nt][1], ba);
            ldsm_x2t(bl[nt][0], bl[nt][1], ba + (PJ_BL - PJ_BH));
        }
        int kb = ks * 2 + (lane >> 4);
#pragma unroll
        for (int mt = 0; mt < 4; ++mt) {
            int rr = wm * 64 + mt * 16 + (lane & 15);
            uint32_t slot = (uint32_t)((kb ^ (rr & 3)) | (rr & 4));
            uint32_t aa = sb + PJ_AH + rr * 128 + slot * 16;
            uint32_t ah0, ah1, ah2, ah3, al0, al1, al2, al3;
            ldsm_x4(ah0, ah1, ah2, ah3, aa);
            ldsm_x4(al0, al1, al2, al3, aa + (PJ_AL - PJ_AH));
#pragma unroll
            for (int nt = 0; nt < 4; ++nt) {
                mma16816(acc[mt][nt], ah0, ah1, ah2, ah3, bh[nt][0], bh[nt][1]);
                mma16816(acc[mt][nt], ah0, ah1, ah2, ah3, bl[nt][0], bl[nt][1]);
                mma16816(acc[mt][nt], al0, al1, al2, al3, bh[nt][0], bh[nt][1]);
            }
        }
    }
    __syncthreads();   // operands dead; reuse region for fp16 stage + red

    uint32_t* sth = (uint32_t*)(sm);
    float* red = (float*)(sm + PJ_RED);
    int slot = wm * 8 + (lane >> 2);
    int npb = wn * 16 + (lane & 3);
#pragma unroll
    for (int nt = 0; nt < 4; ++nt) {
        float se = 0.f, so = 0.f;
        int np = npb + nt * 4;
#pragma unroll
        for (int mt = 0; mt < 4; ++mt) {
            float* c = acc[mt][nt];
            int mlo = wm * 64 + mt * 16 + (lane >> 2);
            float p0 = __expf(fmaxf(c[0], 0.f));
            float p1 = __expf(fmaxf(c[1], 0.f));
            float p2 = __expf(fmaxf(c[2], 0.f));
            float p3 = __expf(fmaxf(c[3], 0.f));
            se += p0 + p2; so += p1 + p3;
            __half2 h01 = __floats2half2_rn(p0, p1);
            __half2 h23 = __floats2half2_rn(p2, p3);
            sth[mlo * 68 + np] = *(uint32_t*)&h01;
            sth[(mlo + 8) * 68 + np] = *(uint32_t*)&h23;
        }
        *(float2*)&red[slot * 132 + wn * 32 + nt * 8 + (lane & 3) * 2] = make_float2(se, so);
    }
    __syncthreads();

    size_t wbase = (size_t)i0 * (NV / 2) + (n0 >> 1);
#pragma unroll
    for (int it = 0; it < 8; ++it) {
        int idx = tid + it * 256;
        int row = idx >> 4, cb = idx & 15;
        *(uint4*)&g_Ph32[wbase + (size_t)row * (NV / 2) + cb * 4] = *(uint4*)&sth[row * 68 + cb * 4];
    }
    if (tid < 128) {
        float s = 0.f;
#pragma unroll
        for (int q = 0; q < 16; ++q) s += red[q * 132 + tid];
        g_cspart[blockIdx.y * NV + n0 + tid] = s;
    }
}

// ========== K2b: rowsum reduce -> 4096/rowsum ==========
__global__ void k_rsum() {
    int n = blockIdx.x * 64 + threadIdx.x;
    float s = 0.f;
#pragma unroll
    for (int mb = 0; mb < 64; ++mb) s += g_cspart[mb * NV + n];
    g_rinv[n] = 4096.0f / s;
}

// ========== K3: B[n][r] = x[bc][n][t] * (4096/rowsum[n]) as fp16 (coalesced) ==========
__global__ __launch_bounds__(256) void k_xs(const float* __restrict__ x) {
    __shared__ float sx[32 * 193];
    __shared__ float sinv[32];
    int tid = threadIdx.x;
    int n0 = blockIdx.x * 32;
    if (tid < 32) sinv[tid] = g_rinv[n0 + tid];
#pragma unroll
    for (int bc = 0; bc < 16; ++bc) {
        const float* src = x + ((size_t)bc * NV + n0) * TV;
        for (int i = tid; i < 32 * TV; i += 256) {
            int nl = i / TV, t = i - nl * TV;
            sx[nl * 193 + bc * TV + t] = src[i];
        }
    }
    __syncthreads();
#pragma unroll
    for (int it = 0; it < 12; ++it) {
        int idx = tid + it * 256;
        int nl = idx / 96, rp = idx - nl * 96;
        float inv = sinv[nl];
        __half2 hh = __floats2half2_rn(sx[nl * 193 + 2 * rp] * inv,
                                       sx[nl * 193 + 2 * rp + 1] * inv);
        g_Bh32[(n0 + nl) * 96 + rp] = *(uint32_t*)&hh;
    }
}

// ========== K4: fp16 HMMA GEMM  C[m][r] = sum_n P[m][n]*xs[n][r] ==========
// grid (64, 2), 512 thr = 16 warps (2 wm x 8 wn, 24 r per warp).
// CTA 128m x 192r, k-chunk 64, 4-stage cp.async.
#define G_BH 16384
#define G_STAGE (16384 + 25600)   /* 41984 */
#define G_SMEM (4 * G_STAGE)      /* 167936 */

__device__ __forceinline__ void g5_load(uint32_t sbase, int stage, int i0, size_t kg, int tid) {
    uint32_t S = sbase + stage * G_STAGE;
    const char* pa = (const char*)g_Ph32;
    const char* bh = (const char*)g_Bh32;
#pragma unroll
    for (int l = 0; l < 5; ++l) {
        int idx = tid + l * 512;
        if (idx < 1024) {                       // A: 128 rows x 8 chunks, swizzled
            int row = idx >> 3, kb = idx & 7;
            const char* src = pa + ((size_t)(i0 + row) * NV + kg + kb * 8) * 2;
            cp16(S + row * 128 + (((uint32_t)(kb ^ (row & 7))) << 4), src);
        } else if (idx < 2560) {                // B: 64 rows x 24 chunks, stride 400
            int j = idx - 1024;
            int kr = j / 24, cb = j % 24;
            cp16(S + G_BH + kr * 400 + cb * 16, bh + (kg + kr) * 384 + cb * 16);
        }
    }
    asm volatile("cp.async.commit_group;" ::: "memory");
}

__global__ __launch_bounds__(512, 1) void k_gemm5() {
    extern __shared__ char sm[];
    uint32_t sbase = smem_u32(sm);
    const int tid = threadIdx.x, lane = tid & 31, wid = tid >> 5;
    const int wm = wid & 1;           // 64-row half
    const int wn = wid >> 1;          // 0..7 -> 24-col slice
    const int i0 = blockIdx.x * 128;
    const size_t k0 = (size_t)blockIdx.y * 4096;

    float acc[4][3][4];
#pragma unroll
    for (int mt = 0; mt < 4; ++mt)
#pragma unroll
        for (int nt = 0; nt < 3; ++nt)
#pragma unroll
            for (int q = 0; q < 4; ++q) acc[mt][nt][q] = 0.f;

    g5_load(sbase, 0, i0, k0, tid);
    g5_load(sbase, 1, i0, k0 + 64, tid);
    g5_load(sbase, 2, i0, k0 + 128, tid);

    for (int c = 0; c < 64; ++c) {
        if (c + 3 < 64) g5_load(sbase, (c + 3) & 3, i0, k0 + (size_t)(c + 3) * 64, tid);
        else asm volatile("cp.async.commit_group;" ::: "memory");
        asm volatile("cp.async.wait_group 3;" ::: "memory");
        __syncthreads();

        uint32_t A = sbase + (c & 3) * G_STAGE;
        uint32_t B = A + G_BH;
#pragma unroll
        for (int ks = 0; ks < 4; ++ks) {
            int krow = ks * 16 + (lane & 15);
            uint32_t bm[4], b4, b5;
            ldsm_x4t(bm[0], bm[1], bm[2], bm[3],
                     B + krow * 400 + (wn * 24 + (lane >> 4) * 8) * 2);
            ldsm_x2t(b4, b5, B + krow * 400 + (wn * 24 + 16) * 2);
            int kb = ks * 2 + (lane >> 4);
#pragma unroll
            for (int mt = 0; mt < 4; ++mt) {
                int rr = wm * 64 + mt * 16 + (lane & 15);
                uint32_t aa = A + rr * 128 + (((uint32_t)(kb ^ (rr & 7))) << 4);
                uint32_t a0, a1, a2, a3;
                ldsm_x4(a0, a1, a2, a3, aa);
                mma16816h(acc[mt][0], a0, a1, a2, a3, bm[0], bm[1]);
                mma16816h(acc[mt][1], a0, a1, a2, a3, bm[2], bm[3]);
                mma16816h(acc[mt][2], a0, a1, a2, a3, b4, b5);
            }
        }
        __syncthreads();
    }

    float* outp = g_part2 + (size_t)blockIdx.y * NV * RV;
#pragma unroll
    for (int mt = 0; mt < 4; ++mt) {
#pragma unroll
        for (int nt = 0; nt < 3; ++nt) {
            int m = i0 + wm * 64 + mt * 16 + (lane >> 2);
            int r = wn * 24 + nt * 8 + (lane & 3) * 2;
            *(float2*)&outp[(size_t)m * RV + r] = make_float2(acc[mt][nt][0], acc[mt][nt][1]);
            *(float2*)&outp[(size_t)(m + 8) * RV + r] = make_float2(acc[mt][nt][2], acc[mt][nt][3]);
        }
    }
}

// ========== K5: reduce 2 split-K partials (undo 4096 scale), 48B/thread ==========
__global__ __launch_bounds__(256) void k_out3(float* __restrict__ out) {
    int bid = blockIdx.x;                    // 512 = 16 bc x 32 m-blocks
    int bc = bid >> 5, mb = bid & 31;
    int m = mb * 256 + threadIdx.x;
    const float* p0 = g_part2 + (size_t)m * RV + bc * TV;
    const float* p1 = p0 + (size_t)NV * RV;
    const float sc = 1.0f / 4096.0f;
    float4 r0 = *(const float4*)p0;
    float4 r1 = *(const float4*)(p0 + 4);
    float4 r2 = *(const float4*)(p0 + 8);
    float4 s0 = *(const float4*)p1;
    float4 s1 = *(const float4*)(p1 + 4);
    float4 s2 = *(const float4*)(p1 + 8);
    r0.x = (r0.x + s0.x) * sc; r0.y = (r0.y + s0.y) * sc;
    r0.z = (r0.z + s0.z) * sc; r0.w = (r0.w + s0.w) * sc;
    r1.x = (r1.x + s1.x) * sc; r1.y = (r1.y + s1.y) * sc;
    r1.z = (r1.z + s1.z) * sc; r1.w = (r1.w + s1.w) * sc;
    r2.x = (r2.x + s2.x) * sc; r2.y = (r2.y + s2.y) * sc;
    r2.z = (r2.z + s2.z) * sc; r2.w = (r2.w + s2.w) * sc;
    float* o = out + ((size_t)bc * NV + m) * TV;
    *(float4*)o = r0;
    *(float4*)(o + 4) = r1;
    *(float4*)(o + 8) = r2;
}

extern "C" void kernel_launch(void* const* d_in, const int* in_sizes, int n_in,
                              void* d_out, int out_size) {
    const float* x    = (const float*)d_in[0];
    const float* nv1  = (const float*)d_in[1];
    const float* nv2  = (const float*)d_in[2];
    const float* tvv  = (const float*)d_in[3];
    const float* kk   = (const float*)d_in[4];
    const int*   tind = (const int*)d_in[5];
    float* out = (float*)d_out;

    cudaFuncSetAttribute(k_gemm5, cudaFuncAttributeMaxDynamicSharedMemorySize, G_SMEM);
    cudaFuncSetAttribute(k_padj_mma, cudaFuncAttributeMaxDynamicSharedMemorySize, PJ_SMEM);

    k_core<<<1, 1024>>>(tvv, kk, tind);
    k_amat<<<NV / 8, 256>>>(nv1);
    k_split<<<2 * NV * DV / 256, 256>>>(nv2);
    k_padj_mma<<<dim3(64, 64), 256, PJ_SMEM>>>();
    k_rsum<<<NV / 64, 64>>>();
    k_xs<<<NV / 32, 256>>>(x);
    k_gemm5<<<dim3(64, 2), 512, G_SMEM>>>();
    k_out3<<<512, 256>>>(out);
}

// round 15
// speedup vs baseline: 1.8453x; 1.0552x over previous
#include <cuda_runtime.h>
#include <cuda_bf16.h>
#include <cuda_fp16.h>
#include <cstdint>

#define NV 8192
#define DV 32
#define TV 12
#define RV 192   /* B*C*T = 2*8*12 */

// ---------------- device scratch (no cudaMalloc anywhere) ----------------
__device__ float    g_core[DV * DV];
__device__ float    g_aT[DV * NV];                    // a transposed [f][n]
__device__ __half   g_A2h[NV * DV];                   // nv2 hi fp16 [m][k]
__device__ __half   g_A2l[NV * DV];                   // nv2 lo fp16
__device__ __half   g_aTh[DV * NV];                   // aT hi fp16 [k][n]
__device__ uint32_t g_Ph32[(size_t)NV * NV / 2];      // Pt fp16 pairs [m][n], 128MB
__device__ uint32_t g_Bh32[NV * 96];                  // xs fp16 pairs [n][r] (x4096)
__device__ float    g_cspart[64 * NV];                // column-sum partials per m-block
__device__ float    g_part2[2ULL * NV * RV];          // split-k partials fp32

// ---------------- mma / ldmatrix / cp.async helpers (plain sm_80+ PTX) ----------------
__device__ __forceinline__ uint32_t smem_u32(const void* p) {
    uint32_t a;
    asm("{ .reg .u64 t; cvta.to.shared.u64 t, %1; cvt.u32.u64 %0, t; }" : "=r"(a) : "l"(p));
    return a;
}
__device__ __forceinline__ void ldsm_x4(uint32_t &r0, uint32_t &r1, uint32_t &r2, uint32_t &r3,
                                        uint32_t a) {
    asm volatile("ldmatrix.sync.aligned.m8n8.x4.shared.b16 {%0,%1,%2,%3}, [%4];"
                 : "=r"(r0), "=r"(r1), "=r"(r2), "=r"(r3) : "r"(a));
}
__device__ __forceinline__ void ldsm_x4t(uint32_t &r0, uint32_t &r1, uint32_t &r2, uint32_t &r3,
                                         uint32_t a) {
    asm volatile("ldmatrix.sync.aligned.m8n8.x4.trans.shared.b16 {%0,%1,%2,%3}, [%4];"
                 : "=r"(r0), "=r"(r1), "=r"(r2), "=r"(r3) : "r"(a));
}
__device__ __forceinline__ void ldsm_x2t(uint32_t &r0, uint32_t &r1, uint32_t a) {
    asm volatile("ldmatrix.sync.aligned.m8n8.x2.trans.shared.b16 {%0,%1}, [%2];"
                 : "=r"(r0), "=r"(r1) : "r"(a));
}
__device__ __forceinline__ void mma16816h(float* c, uint32_t a0, uint32_t a1, uint32_t a2,
                                          uint32_t a3, uint32_t b0, uint32_t b1) {
    asm volatile(
        "mma.sync.aligned.m16n8k16.row.col.f32.f16.f16.f32 "
        "{%0,%1,%2,%3}, {%4,%5,%6,%7}, {%8,%9}, {%0,%1,%2,%3};"
        : "+f"(c[0]), "+f"(c[1]), "+f"(c[2]), "+f"(c[3])
        : "r"(a0), "r"(a1), "r"(a2), "r"(a3), "r"(b0), "r"(b1));
}
__device__ __forceinline__ void cp16(uint32_t d, const void* s) {
    asm volatile("cp.async.cg.shared.global [%0], [%1], 16;" :: "r"(d), "l"(s) : "memory");
}

// ========== K1a: core[e][f] = sum_d tv[d]*k[d][e][f] ==========
__global__ void k_core(const float* __restrict__ timevec, const float* __restrict__ kk,
                       const int* __restrict__ tind) {
    int e = threadIdx.x >> 5, f = threadIdx.x & 31;
    int ti = tind[0];
    float s = 0.f;
#pragma unroll
    for (int d = 0; d < DV; ++d) s += timevec[ti * DV + d] * kk[(d * DV + e) * DV + f];
    g_core[e * DV + f] = s;
}

// ========== K1b: aT[f][n] = sum_e nv1[n][e]*core[e][f] ==========
__global__ void k_amat(const float* __restrict__ nv1) {
    __shared__ float sc[DV * DV];
    int tid = threadIdx.x;
    for (int i = tid; i < DV * DV; i += 256) sc[i] = g_core[i];
    __syncthreads();
    int n = blockIdx.x * 8 + (tid >> 5);
    int f = tid & 31;
    float s = 0.f;
#pragma unroll
    for (int e = 0; e < DV; ++e) s += nv1[n * DV + e] * sc[e * DV + f];
    g_aT[f * NV + n] = s;
}

// ========== K1c: fp16 hi/lo pre-split of nv2; fp16 hi of aT ==========
__global__ void k_split(const float* __restrict__ nv2) {
    int idx = blockIdx.x * 256 + threadIdx.x;
    if (idx < NV * DV) {
        float v = nv2[idx];
        __half h = __float2half_rn(v);
        g_A2h[idx] = h;
        g_A2l[idx] = __float2half_rn(v - __half2float(h));
    } else {
        int j = idx - NV * DV;
        g_aTh[j] = __float2half_rn(g_aT[j]);
    }
}

// ========== K2: fp16 2-product logit GEMM + exp + fp16 store + colsum ==========
// grid (64 nblk, 64 mblk), CTA 128m x 128n, 256 thr = 8 warps (wm 2 x wn 4).
// smem: A2h 16K | A2l 16K | aTh 8704; epilogue reuses region (sth 34816 + red 8448)
#define PJ_AL 16384
#define PJ_BH 32768
#define PJ_RED 34816
#define PJ_SMEM 43264

__global__ __launch_bounds__(256) void k_padj_mma() {
    extern __shared__ char sm[];
    uint32_t sb = smem_u32(sm);
    const int tid = threadIdx.x, lane = tid & 31, wid = tid >> 5;
    const int wm = wid & 1;
    const int wn = wid >> 1;
    const int n0 = blockIdx.x * 128;
    const int i0 = blockIdx.y * 128;

#pragma unroll
    for (int l = 0; l < 4; ++l) {
        int idx = tid + l * 256;                 // 1024 = 2 halves x 128 rows x 4 chunks
        int half = idx >> 9, j = idx & 511;
        int r = j >> 2, kb = j & 3;
        const __half* src = (half ? g_A2l : g_A2h) + (size_t)(i0 + r) * DV + kb * 8;
        uint32_t slot = (uint32_t)((kb ^ (r & 3)) | (r & 4));
        cp16(sb + half * PJ_AL + r * 128 + slot * 16, src);
    }
#pragma unroll
    for (int l = 0; l < 2; ++l) {
        int idx = tid + l * 256;                 // 512 = 32 rows x 16 chunks (hi only)
        int kr = idx >> 4, cb = idx & 15;
        const __half* src = g_aTh + (size_t)kr * NV + n0 + cb * 8;
        cp16(sb + PJ_BH + kr * 272 + cb * 16, src);
    }
    asm volatile("cp.async.commit_group;" ::: "memory");
    asm volatile("cp.async.wait_group 0;" ::: "memory");
    __syncthreads();

    float acc[4][4][4];
#pragma unroll
    for (int mt = 0; mt < 4; ++mt)
#pragma unroll
        for (int nt = 0; nt < 4; ++nt)
#pragma unroll
            for (int q = 0; q < 4; ++q) acc[mt][nt][q] = 0.f;

#pragma unroll
    for (int ks = 0; ks < 2; ++ks) {
        uint32_t bh[4][2];
        int krow = ks * 16 + (lane & 15);
#pragma unroll
        for (int nt = 0; nt < 4; ++nt)
            ldsm_x2t(bh[nt][0], bh[nt][1], sb + PJ_BH + krow * 272 + (wn * 32 + nt * 8) * 2);
        int kb = ks * 2 + (lane >> 4);
#pragma unroll
        for (int mt = 0; mt < 4; ++mt) {
            int rr = wm * 64 + mt * 16 + (lane & 15);
            uint32_t slot = (uint32_t)((kb ^ (rr & 3)) | (rr & 4));
            uint32_t aa = sb + rr * 128 + (slot << 4);
            uint32_t ah0, ah1, ah2, ah3, al0, al1, al2, al3;
            ldsm_x4(ah0, ah1, ah2, ah3, aa);
            ldsm_x4(al0, al1, al2, al3, aa + PJ_AL);
#pragma unroll
            for (int nt = 0; nt < 4; ++nt) {
                mma16816h(acc[mt][nt], ah0, ah1, ah2, ah3, bh[nt][0], bh[nt][1]);
                mma16816h(acc[mt][nt], al0, al1, al2, al3, bh[nt][0], bh[nt][1]);
            }
        }
    }
    __syncthreads();   // operands dead; reuse region for fp16 stage + red

    uint32_t* sth = (uint32_t*)(sm);
    float* red = (float*)(sm + PJ_RED);
    int slot = wm * 8 + (lane >> 2);
    int npb = wn * 16 + (lane & 3);
#pragma unroll
    for (int nt = 0; nt < 4; ++nt) {
        float se = 0.f, so = 0.f;
        int np = npb + nt * 4;
#pragma unroll
        for (int mt = 0; mt < 4; ++mt) {
            float* c = acc[mt][nt];
            int mlo = wm * 64 + mt * 16 + (lane >> 2);
            float p0 = __expf(fmaxf(c[0], 0.f));
            float p1 = __expf(fmaxf(c[1], 0.f));
            float p2 = __expf(fmaxf(c[2], 0.f));
            float p3 = __expf(fmaxf(c[3], 0.f));
            se += p0 + p2; so += p1 + p3;
            __half2 h01 = __floats2half2_rn(p0, p1);
            __half2 h23 = __floats2half2_rn(p2, p3);
            sth[mlo * 68 + np] = *(uint32_t*)&h01;
            sth[(mlo + 8) * 68 + np] = *(uint32_t*)&h23;
        }
        *(float2*)&red[slot * 132 + wn * 32 + nt * 8 + (lane & 3) * 2] = make_float2(se, so);
    }
    __syncthreads();

    size_t wbase = (size_t)i0 * (NV / 2) + (n0 >> 1);
#pragma unroll
    for (int it = 0; it < 8; ++it) {
        int idx = tid + it * 256;
        int row = idx >> 4, cb = idx & 15;
        *(uint4*)&g_Ph32[wbase + (size_t)row * (NV / 2) + cb * 4] = *(uint4*)&sth[row * 68 + cb * 4];
    }
    if (tid < 128) {
        float s = 0.f;
#pragma unroll
        for (int q = 0; q < 16; ++q) s += red[q * 132 + tid];
        g_cspart[blockIdx.y * NV + n0 + tid] = s;
    }
}

// ========== K3: rowsum reduce + B[n][r] = x[bc][n][t]*(4096/rowsum) fp16 ==========
// 32 n per 256-thr block; fused rowsum reduction + smem transpose.
__global__ __launch_bounds__(256) void k_xs(const float* __restrict__ x) {
    __shared__ float sx[32 * 193];
    __shared__ float sred[256];
    __shared__ float sinv[32];
    int tid = threadIdx.x;
    int n0 = blockIdx.x * 32;

    // rowsum: thread t sums 8 m-blocks for n = n0 + (t>>3)
    {
        int nl = tid >> 3, part = tid & 7;
        float s = 0.f;
#pragma unroll
        for (int q = 0; q < 8; ++q) s += g_cspart[(part * 8 + q) * NV + n0 + nl];
        sred[tid] = s;
    }
#pragma unroll
    for (int bc = 0; bc < 16; ++bc) {
        const float* src = x + ((size_t)bc * NV + n0) * TV;
        for (int i = tid; i < 32 * TV; i += 256) {
            int nl = i / TV, t = i - nl * TV;
            sx[nl * 193 + bc * TV + t] = src[i];
        }
    }
    __syncthreads();
    if (tid < 32) {
        float s = 0.f;
#pragma unroll
        for (int q = 0; q < 8; ++q) s += sred[tid * 8 + q];
        sinv[tid] = 4096.0f / s;
    }
    __syncthreads();
#pragma unroll
    for (int it = 0; it < 12; ++it) {
        int idx = tid + it * 256;
        int nl = idx / 96, rp = idx - nl * 96;
        float inv = sinv[nl];
        __half2 hh = __floats2half2_rn(sx[nl * 193 + 2 * rp] * inv,
                                       sx[nl * 193 + 2 * rp + 1] * inv);
        g_Bh32[(n0 + nl) * 96 + rp] = *(uint32_t*)&hh;
    }
}

// ========== K4: fp16 HMMA GEMM  C[m][r] = sum_n P[m][n]*xs[n][r] ==========
// grid (64, 2), 512 thr = 16 warps (2 wm x 8 wn, 24 r per warp).
// CTA 128m x 192r, k-chunk 64, 4-stage cp.async.
#define G_BH 16384
#define G_STAGE (16384 + 25600)   /* 41984 */
#define G_SMEM (4 * G_STAGE)      /* 167936 */

__device__ __forceinline__ void g5_load(uint32_t sbase, int stage, int i0, size_t kg, int tid) {
    uint32_t S = sbase + stage * G_STAGE;
    const char* pa = (const char*)g_Ph32;
    const char* bh = (const char*)g_Bh32;
#pragma unroll
    for (int l = 0; l < 5; ++l) {
        int idx = tid + l * 512;
        if (idx < 1024) {                       // A: 128 rows x 8 chunks, swizzled
            int row = idx >> 3, kb = idx & 7;
            const char* src = pa + ((size_t)(i0 + row) * NV + kg + kb * 8) * 2;
            cp16(S + row * 128 + (((uint32_t)(kb ^ (row & 7))) << 4), src);
        } else if (idx < 2560) {                // B: 64 rows x 24 chunks, stride 400
            int j = idx - 1024;
            int kr = j / 24, cb = j % 24;
            cp16(S + G_BH + kr * 400 + cb * 16, bh + (kg + kr) * 384 + cb * 16);
        }
    }
    asm volatile("cp.async.commit_group;" ::: "memory");
}

__global__ __launch_bounds__(512, 1) void k_gemm5() {
    extern __shared__ char sm[];
    uint32_t sbase = smem_u32(sm);
    const int tid = threadIdx.x, lane = tid & 31, wid = tid >> 5;
    const int wm = wid & 1;           // 64-row half
    const int wn = wid >> 1;          // 0..7 -> 24-col slice
    const int i0 = blockIdx.x * 128;
    const size_t k0 = (size_t)blockIdx.y * 4096;

    float acc[4][3][4];
#pragma unroll
    for (int mt = 0; mt < 4; ++mt)
#pragma unroll
        for (int nt = 0; nt < 3; ++nt)
#pragma unroll
            for (int q = 0; q < 4; ++q) acc[mt][nt][q] = 0.f;

    g5_load(sbase, 0, i0, k0, tid);
    g5_load(sbase, 1, i0, k0 + 64, tid);
    g5_load(sbase, 2, i0, k0 + 128, tid);

    for (int c = 0; c < 64; ++c) {
        if (c + 3 < 64) g5_load(sbase, (c + 3) & 3, i0, k0 + (size_t)(c + 3) * 64, tid);
        else asm volatile("cp.async.commit_group;" ::: "memory");
        asm volatile("cp.async.wait_group 3;" ::: "memory");
        __syncthreads();

        uint32_t A = sbase + (c & 3) * G_STAGE;
        uint32_t B = A + G_BH;
#pragma unroll
        for (int ks = 0; ks < 4; ++ks) {
            int krow = ks * 16 + (lane & 15);
            uint32_t bm[4], b4, b5;
            ldsm_x4t(bm[0], bm[1], bm[2], bm[3],
                     B + krow * 400 + (wn * 24 + (lane >> 4) * 8) * 2);
            ldsm_x2t(b4, b5, B + krow * 400 + (wn * 24 + 16) * 2);
            int kb = ks * 2 + (lane >> 4);
#pragma unroll
            for (int mt = 0; mt < 4; ++mt) {
                int rr = wm * 64 + mt * 16 + (lane & 15);
                uint32_t aa = A + rr * 128 + (((uint32_t)(kb ^ (rr & 7))) << 4);
                uint32_t a0, a1, a2, a3;
                ldsm_x4(a0, a1, a2, a3, aa);
                mma16816h(acc[mt][0], a0, a1, a2, a3, bm[0], bm[1]);
                mma16816h(acc[mt][1], a0, a1, a2, a3, bm[2], bm[3]);
                mma16816h(acc[mt][2], a0, a1, a2, a3, b4, b5);
            }
        }
        __syncthreads();
    }

    float* outp = g_part2 + (size_t)blockIdx.y * NV * RV;
#pragma unroll
    for (int mt = 0; mt < 4; ++mt) {
#pragma unroll
        for (int nt = 0; nt < 3; ++nt) {
            int m = i0 + wm * 64 + mt * 16 + (lane >> 2);
            int r = wn * 24 + nt * 8 + (lane & 3) * 2;
            *(float2*)&outp[(size_t)m * RV + r] = make_float2(acc[mt][nt][0], acc[mt][nt][1]);
            *(float2*)&outp[(size_t)(m + 8) * RV + r] = make_float2(acc[mt][nt][2], acc[mt][nt][3]);
        }
    }
}

// ========== K5: reduce 2 split-K partials (undo 4096 scale), 48B/thread ==========
__global__ __launch_bounds__(256) void k_out3(float* __restrict__ out) {
    int bid = blockIdx.x;                    // 512 = 16 bc x 32 m-blocks
    int bc = bid >> 5, mb = bid & 31;
    int m = mb * 256 + threadIdx.x;
    const float* p0 = g_part2 + (size_t)m * RV + bc * TV;
    const float* p1 = p0 + (size_t)NV * RV;
    const float sc = 1.0f / 4096.0f;
    float4 r0 = *(const float4*)p0;
    float4 r1 = *(const float4*)(p0 + 4);
    float4 r2 = *(const float4*)(p0 + 8);
    float4 s0 = *(const float4*)p1;
    float4 s1 = *(const float4*)(p1 + 4);
    float4 s2 = *(const float4*)(p1 + 8);
    r0.x = (r0.x + s0.x) * sc; r0.y = (r0.y + s0.y) * sc;
    r0.z = (r0.z + s0.z) * sc; r0.w = (r0.w + s0.w) * sc;
    r1.x = (r1.x + s1.x) * sc; r1.y = (r1.y + s1.y) * sc;
    r1.z = (r1.z + s1.z) * sc; r1.w = (r1.w + s1.w) * sc;
    r2.x = (r2.x + s2.x) * sc; r2.y = (r2.y + s2.y) * sc;
    r2.z = (r2.z + s2.z) * sc; r2.w = (r2.w + s2.w) * sc;
    float* o = out + ((size_t)bc * NV + m) * TV;
    *(float4*)o = r0;
    *(float4*)(o + 4) = r1;
    *(float4*)(o + 8) = r2;
}

extern "C" void kernel_launch(void* const* d_in, const int* in_sizes, int n_in,
                              void* d_out, int out_size) {
    const float* x    = (const float*)d_in[0];
    const float* nv1  = (const float*)d_in[1];
    const float* nv2  = (const float*)d_in[2];
    const float* tvv  = (const float*)d_in[3];
    const float* kk   = (const float*)d_in[4];
    const int*   tind = (const int*)d_in[5];
    float* out = (float*)d_out;

    cudaFuncSetAttribute(k_gemm5, cudaFuncAttributeMaxDynamicSharedMemorySize, G_SMEM);
    cudaFuncSetAttribute(k_padj_mma, cudaFuncAttributeMaxDynamicSharedMemorySize, PJ_SMEM);

    k_core<<<1, 1024>>>(tvv, kk, tind);
    k_amat<<<NV / 8, 256>>>(nv1);
    k_split<<<2 * NV * DV / 256, 256>>>(nv2);
    k_padj_mma<<<dim3(64, 64), 256, PJ_SMEM>>>();
    k_xs<<<NV / 32, 256>>>(x);
    k_gemm5<<<dim3(64, 2), 512, G_SMEM>>>();
    k_out3<<<512, 256>>>(out);
}

// round 16
// speedup vs baseline: 1.8842x; 1.0211x over previous
#include <cuda_runtime.h>
#include <cuda_bf16.h>
#include <cuda_fp16.h>
#include <cstdint>

#define NV 8192
#define DV 32
#define TV 12
#define RV 192   /* B*C*T = 2*8*12 */

// ---------------- device scratch (no cudaMalloc anywhere) ----------------
__device__ float    g_core[DV * DV];
__device__ __half   g_A2h[NV * DV];                   // nv2 hi fp16 [m][k]
__device__ __half   g_A2l[NV * DV];                   // nv2 lo fp16
__device__ __half   g_aTh[DV * NV];                   // aT hi fp16 [k][n]
__device__ uint32_t g_Ph32[(size_t)NV * NV / 2];      // Pt fp16 pairs [m][n], 128MB
__device__ uint32_t g_Bh32[NV * 96];                  // xs fp16 pairs [n][r] (x4096)
__device__ float    g_cspart[64 * NV];                // column-sum partials per m-block
__device__ float    g_part2[2ULL * NV * RV];          // split-k partials fp32

// ---------------- mma / ldmatrix / cp.async helpers (plain sm_80+ PTX) ----------------
__device__ __forceinline__ uint32_t smem_u32(const void* p) {
    uint32_t a;
    asm("{ .reg .u64 t; cvta.to.shared.u64 t, %1; cvt.u32.u64 %0, t; }" : "=r"(a) : "l"(p));
    return a;
}
__device__ __forceinline__ void ldsm_x4(uint32_t &r0, uint32_t &r1, uint32_t &r2, uint32_t &r3,
                                        uint32_t a) {
    asm volatile("ldmatrix.sync.aligned.m8n8.x4.shared.b16 {%0,%1,%2,%3}, [%4];"
                 : "=r"(r0), "=r"(r1), "=r"(r2), "=r"(r3) : "r"(a));
}
__device__ __forceinline__ void ldsm_x4t(uint32_t &r0, uint32_t &r1, uint32_t &r2, uint32_t &r3,
                                         uint32_t a) {
    asm volatile("ldmatrix.sync.aligned.m8n8.x4.trans.shared.b16 {%0,%1,%2,%3}, [%4];"
                 : "=r"(r0), "=r"(r1), "=r"(r2), "=r"(r3) : "r"(a));
}
__device__ __forceinline__ void ldsm_x2t(uint32_t &r0, uint32_t &r1, uint32_t a) {
    asm volatile("ldmatrix.sync.aligned.m8n8.x2.trans.shared.b16 {%0,%1}, [%2];"
                 : "=r"(r0), "=r"(r1) : "r"(a));
}
__device__ __forceinline__ void mma16816h(float* c, uint32_t a0, uint32_t a1, uint32_t a2,
                                          uint32_t a3, uint32_t b0, uint32_t b1) {
    asm volatile(
        "mma.sync.aligned.m16n8k16.row.col.f32.f16.f16.f32 "
        "{%0,%1,%2,%3}, {%4,%5,%6,%7}, {%8,%9}, {%0,%1,%2,%3};"
        : "+f"(c[0]), "+f"(c[1]), "+f"(c[2]), "+f"(c[3])
        : "r"(a0), "r"(a1), "r"(a2), "r"(a3), "r"(b0), "r"(b1));
}
__device__ __forceinline__ void cp16(uint32_t d, const void* s) {
    asm volatile("cp.async.cg.shared.global [%0], [%1], 16;" :: "r"(d), "l"(s) : "memory");
}

// ========== K1a: core[e][f] = sum_d tv[d]*k[d][e][f] ==========
__global__ void k_core(const float* __restrict__ timevec, const float* __restrict__ kk,
                       const int* __restrict__ tind) {
    int e = threadIdx.x >> 5, f = threadIdx.x & 31;
    int ti = tind[0];
    float s = 0.f;
#pragma unroll
    for (int d = 0; d < DV; ++d) s += timevec[ti * DV + d] * kk[(d * DV + e) * DV + f];
    g_core[e * DV + f] = s;
}

// ========== K1b: aTh[f][n] = fp16(sum_e nv1[n][e]*core[e][f]);  A2 hi/lo from nv2 ==========
__global__ void k_amat(const float* __restrict__ nv1, const float* __restrict__ nv2) {
    __shared__ float sc[DV * DV];
    int tid = threadIdx.x;
    for (int i = tid; i < DV * DV; i += 256) sc[i] = g_core[i];
    __syncthreads();
    int n = blockIdx.x * 8 + (tid >> 5);
    int f = tid & 31;
    float s = 0.f;
#pragma unroll
    for (int e = 0; e < DV; ++e) s += nv1[n * DV + e] * sc[e * DV + f];
    g_aTh[f * NV + n] = __float2half_rn(s);
    float v = nv2[n * DV + f];
    __half h = __float2half_rn(v);
    g_A2h[n * DV + f] = h;
    g_A2l[n * DV + f] = __float2half_rn(v - __half2float(h));
}

// ========== K2: fp16 2-product logit GEMM + exp + fp16 store + colsum ==========
// grid (32 nstrip of 256, 64 mblk), CTA 128m x 256n in two 128n chunks, 256 thr.
// smem: A2h 16K | A2l 16K | aTh chunk0 8704 | aTh chunk1 8704 | sth 34816 | red 8448
#define PJ_AL 16384
#define PJ_B0 32768
#define PJ_B1 41472
#define PJ_ST 50176
#define PJ_RED 84992
#define PJ_SMEM 93440

__global__ __launch_bounds__(256) void k_padj_mma() {
    extern __shared__ char sm[];
    uint32_t sb = smem_u32(sm);
    const int tid = threadIdx.x, lane = tid & 31, wid = tid >> 5;
    const int wm = wid & 1;
    const int wn = wid >> 1;
    const int n0 = blockIdx.x * 256;
    const int i0 = blockIdx.y * 128;

    // group A: A2 hi/lo + aTh chunk0
#pragma unroll
    for (int l = 0; l < 4; ++l) {
        int idx = tid + l * 256;                 // 1024 = 2 halves x 128 rows x 4 chunks
        int half = idx >> 9, j = idx & 511;
        int r = j >> 2, kb = j & 3;
        const __half* src = (half ? g_A2l : g_A2h) + (size_t)(i0 + r) * DV + kb * 8;
        uint32_t slot = (uint32_t)((kb ^ (r & 3)) | (r & 4));
        cp16(sb + half * PJ_AL + r * 128 + slot * 16, src);
    }
#pragma unroll
    for (int l = 0; l < 2; ++l) {
        int idx = tid + l * 256;                 // 512 = 32 rows x 16 chunks
        int kr = idx >> 4, cb = idx & 15;
        cp16(sb + PJ_B0 + kr * 272 + cb * 16, g_aTh + (size_t)kr * NV + n0 + cb * 8);
    }
    asm volatile("cp.async.commit_group;" ::: "memory");
    // group B: aTh chunk1
#pragma unroll
    for (int l = 0; l < 2; ++l) {
        int idx = tid + l * 256;
        int kr = idx >> 4, cb = idx & 15;
        cp16(sb + PJ_B1 + kr * 272 + cb * 16, g_aTh + (size_t)kr * NV + n0 + 128 + cb * 8);
    }
    asm volatile("cp.async.commit_group;" ::: "memory");
    asm volatile("cp.async.wait_group 1;" ::: "memory");
    __syncthreads();

    uint32_t* sth = (uint32_t*)(sm + PJ_ST);
    float* red = (float*)(sm + PJ_RED);

#pragma unroll
    for (int ch = 0; ch < 2; ++ch) {
        if (ch == 1) {
            asm volatile("cp.async.wait_group 0;" ::: "memory");
            __syncthreads();                     // chunk1 data visible; sth free (copy-out done)
        }
        int n0c = n0 + ch * 128;
        uint32_t BB = sb + PJ_B0 + ch * 8704;

        float acc[4][4][4];
#pragma unroll
        for (int mt = 0; mt < 4; ++mt)
#pragma unroll
            for (int nt = 0; nt < 4; ++nt)
#pragma unroll
                for (int q = 0; q < 4; ++q) acc[mt][nt][q] = 0.f;

#pragma unroll
        for (int ks = 0; ks < 2; ++ks) {
            uint32_t bh[4][2];
            int krow = ks * 16 + (lane & 15);
#pragma unroll
            for (int nt = 0; nt < 4; ++nt)
                ldsm_x2t(bh[nt][0], bh[nt][1], BB + krow * 272 + (wn * 32 + nt * 8) * 2);
            int kb = ks * 2 + (lane >> 4);
#pragma unroll
            for (int mt = 0; mt < 4; ++mt) {
                int rr = wm * 64 + mt * 16 + (lane & 15);
                uint32_t slot = (uint32_t)((kb ^ (rr & 3)) | (rr & 4));
                uint32_t aa = sb + rr * 128 + (slot << 4);
                uint32_t ah0, ah1, ah2, ah3, al0, al1, al2, al3;
                ldsm_x4(ah0, ah1, ah2, ah3, aa);
                ldsm_x4(al0, al1, al2, al3, aa + PJ_AL);
#pragma unroll
                for (int nt = 0; nt < 4; ++nt) {
                    mma16816h(acc[mt][nt], ah0, ah1, ah2, ah3, bh[nt][0], bh[nt][1]);
                    mma16816h(acc[mt][nt], al0, al1, al2, al3, bh[nt][0], bh[nt][1]);
                }
            }
        }

        // ---- epilogue: exp + fp16 stage + colsum partial ----
        int slot = wm * 8 + (lane >> 2);
        int npb = wn * 16 + (lane & 3);
#pragma unroll
        for (int nt = 0; nt < 4; ++nt) {
            float se = 0.f, so = 0.f;
            int np = npb + nt * 4;
#pragma unroll
            for (int mt = 0; mt < 4; ++mt) {
                float* c = acc[mt][nt];
                int mlo = wm * 64 + mt * 16 + (lane >> 2);
                float p0 = __expf(fmaxf(c[0], 0.f));
                float p1 = __expf(fmaxf(c[1], 0.f));
                float p2 = __expf(fmaxf(c[2], 0.f));
                float p3 = __expf(fmaxf(c[3], 0.f));
                se += p0 + p2; so += p1 + p3;
                __half2 h01 = __floats2half2_rn(p0, p1);
                __half2 h23 = __floats2half2_rn(p2, p3);
                sth[mlo * 68 + np] = *(uint32_t*)&h01;
                sth[(mlo + 8) * 68 + np] = *(uint32_t*)&h23;
            }
            *(float2*)&red[slot * 132 + wn * 32 + nt * 8 + (lane & 3) * 2] = make_float2(se, so);
        }
        __syncthreads();

        // ---- coalesced copy-out + colsum reduce ----
        size_t wbase = (size_t)i0 * (NV / 2) + (n0c >> 1);
#pragma unroll
        for (int it = 0; it < 8; ++it) {
            int idx = tid + it * 256;
            int row = idx >> 4, cb = idx & 15;
            *(uint4*)&g_Ph32[wbase + (size_t)row * (NV / 2) + cb * 4] =
                *(uint4*)&sth[row * 68 + cb * 4];
        }
        if (tid < 128) {
            float s = 0.f;
#pragma unroll
            for (int q = 0; q < 16; ++q) s += red[q * 132 + tid];
            g_cspart[blockIdx.y * NV + n0c + tid] = s;
        }
        __syncthreads();                         // protect sth/red before next chunk writes
    }
}

// ========== K3: rowsum reduce + B[n][r] = x[bc][n][t]*(4096/rowsum) fp16 ==========
__global__ __launch_bounds__(256) void k_xs(const float* __restrict__ x) {
    __shared__ float sx[32 * 193];
    __shared__ float sred[256];
    __shared__ float sinv[32];
    int tid = threadIdx.x;
    int n0 = blockIdx.x * 32;

    {
        int nl = tid >> 3, part = tid & 7;
        float s = 0.f;
#pragma unroll
        for (int q = 0; q < 8; ++q) s += g_cspart[(part * 8 + q) * NV + n0 + nl];
        sred[tid] = s;
    }
#pragma unroll
    for (int bc = 0; bc < 16; ++bc) {
        const float* src = x + ((size_t)bc * NV + n0) * TV;
        for (int i = tid; i < 32 * TV; i += 256) {
            int nl = i / TV, t = i - nl * TV;
            sx[nl * 193 + bc * TV + t] = src[i];
        }
    }
    __syncthreads();
    if (tid < 32) {
        float s = 0.f;
#pragma unroll
        for (int q = 0; q < 8; ++q) s += sred[tid * 8 + q];
        sinv[tid] = 4096.0f / s;
    }
    __syncthreads();
#pragma unroll
    for (int it = 0; it < 12; ++it) {
        int idx = tid + it * 256;
        int nl = idx / 96, rp = idx - nl * 96;
        float inv = sinv[nl];
        __half2 hh = __floats2half2_rn(sx[nl * 193 + 2 * rp] * inv,
                                       sx[nl * 193 + 2 * rp + 1] * inv);
        g_Bh32[(n0 + nl) * 96 + rp] = *(uint32_t*)&hh;
    }
}

// ========== K4: fp16 HMMA GEMM  C[m][r] = sum_n P[m][n]*xs[n][r] ==========
// grid (64, 2), 512 thr = 16 warps (2 wm x 8 wn, 24 r per warp).
// CTA 128m x 192r, k-chunk 64, 4-stage cp.async.
#define G_BH 16384
#define G_STAGE (16384 + 25600)   /* 41984 */
#define G_SMEM (4 * G_STAGE)      /* 167936 */

__device__ __forceinline__ void g5_load(uint32_t sbase, int stage, int i0, size_t kg, int tid) {
    uint32_t S = sbase + stage * G_STAGE;
    const char* pa = (const char*)g_Ph32;
    const char* bh = (const char*)g_Bh32;
#pragma unroll
    for (int l = 0; l < 5; ++l) {
        int idx = tid + l * 512;
        if (idx < 1024) {                       // A: 128 rows x 8 chunks, swizzled
            int row = idx >> 3, kb = idx & 7;
            const char* src = pa + ((size_t)(i0 + row) * NV + kg + kb * 8) * 2;
            cp16(S + row * 128 + (((uint32_t)(kb ^ (row & 7))) << 4), src);
        } else if (idx < 2560) {                // B: 64 rows x 24 chunks, stride 400
            int j = idx - 1024;
            int kr = j / 24, cb = j % 24;
            cp16(S + G_BH + kr * 400 + cb * 16, bh + (kg + kr) * 384 + cb * 16);
        }
    }
    asm volatile("cp.async.commit_group;" ::: "memory");
}

__global__ __launch_bounds__(512, 1) void k_gemm5() {
    extern __shared__ char sm[];
    uint32_t sbase = smem_u32(sm);
    const int tid = threadIdx.x, lane = tid & 31, wid = tid >> 5;
    const int wm = wid & 1;           // 64-row half
    const int wn = wid >> 1;          // 0..7 -> 24-col slice
    const int i0 = blockIdx.x * 128;
    const size_t k0 = (size_t)blockIdx.y * 4096;

    float acc[4][3][4];
#pragma unroll
    for (int mt = 0; mt < 4; ++mt)
#pragma unroll
        for (int nt = 0; nt < 3; ++nt)
#pragma unroll
            for (int q = 0; q < 4; ++q) acc[mt][nt][q] = 0.f;

    g5_load(sbase, 0, i0, k0, tid);
    g5_load(sbase, 1, i0, k0 + 64, tid);
    g5_load(sbase, 2, i0, k0 + 128, tid);

    for (int c = 0; c < 64; ++c) {
        if (c + 3 < 64) g5_load(sbase, (c + 3) & 3, i0, k0 + (size_t)(c + 3) * 64, tid);
        else asm volatile("cp.async.commit_group;" ::: "memory");
        asm volatile("cp.async.wait_group 3;" ::: "memory");
        __syncthreads();

        uint32_t A = sbase + (c & 3) * G_STAGE;
        uint32_t B = A + G_BH;
#pragma unroll
        for (int ks = 0; ks < 4; ++ks) {
            int krow = ks * 16 + (lane & 15);
            uint32_t bm[4], b4, b5;
            ldsm_x4t(bm[0], bm[1], bm[2], bm[3],
                     B + krow * 400 + (wn * 24 + (lane >> 4) * 8) * 2);
            ldsm_x2t(b4, b5, B + krow * 400 + (wn * 24 + 16) * 2);
            int kb = ks * 2 + (lane >> 4);
#pragma unroll
            for (int mt = 0; mt < 4; ++mt) {
                int rr = wm * 64 + mt * 16 + (lane & 15);
                uint32_t aa = A + rr * 128 + (((uint32_t)(kb ^ (rr & 7))) << 4);
                uint32_t a0, a1, a2, a3;
                ldsm_x4(a0, a1, a2, a3, aa);
                mma16816h(acc[mt][0], a0, a1, a2, a3, bm[0], bm[1]);
                mma16816h(acc[mt][1], a0, a1, a2, a3, bm[2], bm[3]);
                mma16816h(acc[mt][2], a0, a1, a2, a3, b4, b5);
            }
        }
        __syncthreads();
    }

    float* outp = g_part2 + (size_t)blockIdx.y * NV * RV;
#pragma unroll
    for (int mt = 0; mt < 4; ++mt) {
#pragma unroll
        for (int nt = 0; nt < 3; ++nt) {
            int m = i0 + wm * 64 + mt * 16 + (lane >> 2);
            int r = wn * 24 + nt * 8 + (lane & 3) * 2;
            *(float2*)&outp[(size_t)m * RV + r] = make_float2(acc[mt][nt][0], acc[mt][nt][1]);
            *(float2*)&outp[(size_t)(m + 8) * RV + r] = make_float2(acc[mt][nt][2], acc[mt][nt][3]);
        }
    }
}

// ========== K5: reduce 2 split-K partials (undo 4096 scale), 48B/thread ==========
__global__ __launch_bounds__(256) void k_out3(float* __restrict__ out) {
    int bid = blockIdx.x;                    // 512 = 16 bc x 32 m-blocks
    int bc = bid >> 5, mb = bid & 31;
    int m = mb * 256 + threadIdx.x;
    const float* p0 = g_part2 + (size_t)m * RV + bc * TV;
    const float* p1 = p0 + (size_t)NV * RV;
    const float sc = 1.0f / 4096.0f;
    float4 r0 = *(const float4*)p0;
    float4 r1 = *(const float4*)(p0 + 4);
    float4 r2 = *(const float4*)(p0 + 8);
    float4 s0 = *(const float4*)p1;
    float4 s1 = *(const float4*)(p1 + 4);
    float4 s2 = *(const float4*)(p1 + 8);
    r0.x = (r0.x + s0.x) * sc; r0.y = (r0.y + s0.y) * sc;
    r0.z = (r0.z + s0.z) * sc; r0.w = (r0.w + s0.w) * sc;
    r1.x = (r1.x + s1.x) * sc; r1.y = (r1.y + s1.y) * sc;
    r1.z = (r1.z + s1.z) * sc; r1.w = (r1.w + s1.w) * sc;
    r2.x = (r2.x + s2.x) * sc; r2.y = (r2.y + s2.y) * sc;
    r2.z = (r2.z + s2.z) * sc; r2.w = (r2.w + s2.w) * sc;
    float* o = out + ((size_t)bc * NV + m) * TV;
    *(float4*)o = r0;
    *(float4*)(o + 4) = r1;
    *(float4*)(o + 8) = r2;
}

extern "C" void kernel_launch(void* const* d_in, const int* in_sizes, int n_in,
                              void* d_out, int out_size) {
    const float* x    = (const float*)d_in[0];
    const float* nv1  = (const float*)d_in[1];
    const float* nv2  = (const float*)d_in[2];
    const float* tvv  = (const float*)d_in[3];
    const float* kk   = (const float*)d_in[4];
    const int*   tind = (const int*)d_in[5];
    float* out = (float*)d_out;

    cudaFuncSetAttribute(k_gemm5, cudaFuncAttributeMaxDynamicSharedMemorySize, G_SMEM);
    cudaFuncSetAttribute(k_padj_mma, cudaFuncAttributeMaxDynamicSharedMemorySize, PJ_SMEM);

    k_core<<<1, 1024>>>(tvv, kk, tind);
    k_amat<<<NV / 8, 256>>>(nv1, nv2);
    k_padj_mma<<<dim3(32, 64), 256, PJ_SMEM>>>();
    k_xs<<<NV / 32, 256>>>(x);
    k_gemm5<<<dim3(64, 2), 512, G_SMEM>>>();
    k_out3<<<512, 256>>>(out);
}

// round 17
// speedup vs baseline: 2.0023x; 1.0627x over previous
#include <cuda_runtime.h>
#include <cuda_bf16.h>
#include <cuda_fp16.h>
#include <cstdint>

#define NV 8192
#define DV 32
#define TV 12
#define RV 192   /* B*C*T = 2*8*12 */

// ---------------- device scratch (no cudaMalloc anywhere) ----------------
__device__ float    g_core[DV * DV];
__device__ __half   g_A2h[NV * DV];                   // nv2 hi fp16 [m][k]
__device__ __half   g_A2l[NV * DV];                   // nv2 lo fp16
__device__ __half   g_aTh[DV * NV];                   // aT hi fp16 [k][n]
__device__ uint32_t g_Ph32[(size_t)NV * NV / 2];      // Pt fp16 pairs [m][n], 128MB
__device__ uint32_t g_Bh32[NV * 96];                  // xs fp16 pairs [n][r] (x4096)
__device__ float    g_cspart[64 * NV];                // column-sum partials per m-block
__device__ float    g_part2[2ULL * NV * RV];          // split-k partials fp32

// ---------------- mma / ldmatrix / cp.async helpers (plain sm_80+ PTX) ----------------
__device__ __forceinline__ uint32_t smem_u32(const void* p) {
    uint32_t a;
    asm("{ .reg .u64 t; cvta.to.shared.u64 t, %1; cvt.u32.u64 %0, t; }" : "=r"(a) : "l"(p));
    return a;
}
__device__ __forceinline__ void ldsm_x4(uint32_t &r0, uint32_t &r1, uint32_t &r2, uint32_t &r3,
                                        uint32_t a) {
    asm volatile("ldmatrix.sync.aligned.m8n8.x4.shared.b16 {%0,%1,%2,%3}, [%4];"
                 : "=r"(r0), "=r"(r1), "=r"(r2), "=r"(r3) : "r"(a));
}
__device__ __forceinline__ void ldsm_x4t(uint32_t &r0, uint32_t &r1, uint32_t &r2, uint32_t &r3,
                                         uint32_t a) {
    asm volatile("ldmatrix.sync.aligned.m8n8.x4.trans.shared.b16 {%0,%1,%2,%3}, [%4];"
                 : "=r"(r0), "=r"(r1), "=r"(r2), "=r"(r3) : "r"(a));
}
__device__ __forceinline__ void ldsm_x2t(uint32_t &r0, uint32_t &r1, uint32_t a) {
    asm volatile("ldmatrix.sync.aligned.m8n8.x2.trans.shared.b16 {%0,%1}, [%2];"
                 : "=r"(r0), "=r"(r1) : "r"(a));
}
__device__ __forceinline__ void mma16816h(float* c, uint32_t a0, uint32_t a1, uint32_t a2,
                                          uint32_t a3, uint32_t b0, uint32_t b1) {
    asm volatile(
        "mma.sync.aligned.m16n8k16.row.col.f32.f16.f16.f32 "
        "{%0,%1,%2,%3}, {%4,%5,%6,%7}, {%8,%9}, {%0,%1,%2,%3};"
        : "+f"(c[0]), "+f"(c[1]), "+f"(c[2]), "+f"(c[3])
        : "r"(a0), "r"(a1), "r"(a2), "r"(a3), "r"(b0), "r"(b1));
}
__device__ __forceinline__ void cp16(uint32_t d, const void* s) {
    asm volatile("cp.async.cg.shared.global [%0], [%1], 16;" :: "r"(d), "l"(s) : "memory");
}

// ========== K1a: core[e][f] = sum_d tv[d]*k[d][e][f] ==========
__global__ void k_core(const float* __restrict__ timevec, const float* __restrict__ kk,
                       const int* __restrict__ tind) {
    int e = threadIdx.x >> 5, f = threadIdx.x & 31;
    int ti = tind[0];
    float s = 0.f;
#pragma unroll
    for (int d = 0; d < DV; ++d) s += timevec[ti * DV + d] * kk[(d * DV + e) * DV + f];
    g_core[e * DV + f] = s;
}

// ========== K1b: aTh[f][n] = fp16(sum_e nv1[n][e]*core[e][f]);  A2 hi/lo from nv2 ==========
__global__ void k_amat(const float* __restrict__ nv1, const float* __restrict__ nv2) {
    __shared__ float sc[DV * DV];
    int tid = threadIdx.x;
    for (int i = tid; i < DV * DV; i += 256) sc[i] = g_core[i];
    __syncthreads();
    int n = blockIdx.x * 8 + (tid >> 5);
    int f = tid & 31;
    float s = 0.f;
#pragma unroll
    for (int e = 0; e < DV; ++e) s += nv1[n * DV + e] * sc[e * DV + f];
    g_aTh[f * NV + n] = __float2half_rn(s);
    float v = nv2[n * DV + f];
    __half h = __float2half_rn(v);
    g_A2h[n * DV + f] = h;
    g_A2l[n * DV + f] = __float2half_rn(v - __half2float(h));
}

// ========== K2: fp16 2-product logit GEMM + exp + fp16 store + colsum ==========
// grid (32 nstrip of 256, 64 mblk), CTA 128m x 256n in two 128n chunks, 256 thr.
#define PJ_AL 16384
#define PJ_B0 32768
#define PJ_B1 41472
#define PJ_ST 50176
#define PJ_RED 84992
#define PJ_SMEM 93440

__global__ __launch_bounds__(256) void k_padj_mma() {
    extern __shared__ char sm[];
    uint32_t sb = smem_u32(sm);
    const int tid = threadIdx.x, lane = tid & 31, wid = tid >> 5;
    const int wm = wid & 1;
    const int wn = wid >> 1;
    const int n0 = blockIdx.x * 256;
    const int i0 = blockIdx.y * 128;

    // group A: A2 hi/lo + aTh chunk0
#pragma unroll
    for (int l = 0; l < 4; ++l) {
        int idx = tid + l * 256;
        int half = idx >> 9, j = idx & 511;
        int r = j >> 2, kb = j & 3;
        const __half* src = (half ? g_A2l : g_A2h) + (size_t)(i0 + r) * DV + kb * 8;
        uint32_t slot = (uint32_t)((kb ^ (r & 3)) | (r & 4));
        cp16(sb + half * PJ_AL + r * 128 + slot * 16, src);
    }
#pragma unroll
    for (int l = 0; l < 2; ++l) {
        int idx = tid + l * 256;
        int kr = idx >> 4, cb = idx & 15;
        cp16(sb + PJ_B0 + kr * 272 + cb * 16, g_aTh + (size_t)kr * NV + n0 + cb * 8);
    }
    asm volatile("cp.async.commit_group;" ::: "memory");
    // group B: aTh chunk1
#pragma unroll
    for (int l = 0; l < 2; ++l) {
        int idx = tid + l * 256;
        int kr = idx >> 4, cb = idx & 15;
        cp16(sb + PJ_B1 + kr * 272 + cb * 16, g_aTh + (size_t)kr * NV + n0 + 128 + cb * 8);
    }
    asm volatile("cp.async.commit_group;" ::: "memory");
    asm volatile("cp.async.wait_group 1;" ::: "memory");
    __syncthreads();

    uint32_t* sth = (uint32_t*)(sm + PJ_ST);
    float* red = (float*)(sm + PJ_RED);

#pragma unroll
    for (int ch = 0; ch < 2; ++ch) {
        if (ch == 1) {
            asm volatile("cp.async.wait_group 0;" ::: "memory");
            __syncthreads();
        }
        int n0c = n0 + ch * 128;
        uint32_t BB = sb + PJ_B0 + ch * 8704;

        float acc[4][4][4];
#pragma unroll
        for (int mt = 0; mt < 4; ++mt)
#pragma unroll
            for (int nt = 0; nt < 4; ++nt)
#pragma unroll
                for (int q = 0; q < 4; ++q) acc[mt][nt][q] = 0.f;

#pragma unroll
        for (int ks = 0; ks < 2; ++ks) {
            uint32_t bh[4][2];
            int krow = ks * 16 + (lane & 15);
#pragma unroll
            for (int nt = 0; nt < 4; ++nt)
                ldsm_x2t(bh[nt][0], bh[nt][1], BB + krow * 272 + (wn * 32 + nt * 8) * 2);
            int kb = ks * 2 + (lane >> 4);
#pragma unroll
            for (int mt = 0; mt < 4; ++mt) {
                int rr = wm * 64 + mt * 16 + (lane & 15);
                uint32_t slot = (uint32_t)((kb ^ (rr & 3)) | (rr & 4));
                uint32_t aa = sb + rr * 128 + (slot << 4);
                uint32_t ah0, ah1, ah2, ah3, al0, al1, al2, al3;
                ldsm_x4(ah0, ah1, ah2, ah3, aa);
                ldsm_x4(al0, al1, al2, al3, aa + PJ_AL);
#pragma unroll
                for (int nt = 0; nt < 4; ++nt) {
                    mma16816h(acc[mt][nt], ah0, ah1, ah2, ah3, bh[nt][0], bh[nt][1]);
                    mma16816h(acc[mt][nt], al0, al1, al2, al3, bh[nt][0], bh[nt][1]);
                }
            }
        }

        // ---- epilogue: exp + fp16 stage + colsum partial ----
        int slot = wm * 8 + (lane >> 2);
        int npb = wn * 16 + (lane & 3);
#pragma unroll
        for (int nt = 0; nt < 4; ++nt) {
            float se = 0.f, so = 0.f;
            int np = npb + nt * 4;
#pragma unroll
            for (int mt = 0; mt < 4; ++mt) {
                float* c = acc[mt][nt];
                int mlo = wm * 64 + mt * 16 + (lane >> 2);
                float p0 = __expf(fmaxf(c[0], 0.f));
                float p1 = __expf(fmaxf(c[1], 0.f));
                float p2 = __expf(fmaxf(c[2], 0.f));
                float p3 = __expf(fmaxf(c[3], 0.f));
                se += p0 + p2; so += p1 + p3;
                __half2 h01 = __floats2half2_rn(p0, p1);
                __half2 h23 = __floats2half2_rn(p2, p3);
                sth[mlo * 68 + np] = *(uint32_t*)&h01;
                sth[(mlo + 8) * 68 + np] = *(uint32_t*)&h23;
            }
            *(float2*)&red[slot * 132 + wn * 32 + nt * 8 + (lane & 3) * 2] = make_float2(se, so);
        }
        __syncthreads();

        // ---- coalesced copy-out + colsum reduce ----
        size_t wbase = (size_t)i0 * (NV / 2) + (n0c >> 1);
#pragma unroll
        for (int it = 0; it < 8; ++it) {
            int idx = tid + it * 256;
            int row = idx >> 4, cb = idx & 15;
            *(uint4*)&g_Ph32[wbase + (size_t)row * (NV / 2) + cb * 4] =
                *(uint4*)&sth[row * 68 + cb * 4];
        }
        if (tid < 128) {
            float s = 0.f;
#pragma unroll
            for (int q = 0; q < 16; ++q) s += red[q * 132 + tid];
            g_cspart[blockIdx.y * NV + n0c + tid] = s;
        }
        __syncthreads();
    }
}

// ========== K3: rowsum reduce + B[n][r] = x[bc][n][t]*(4096/rowsum) fp16 ==========
// grid (256 nblk of 32, 4 bc-groups of 4). Coalesced rowsum gather (lanes = n).
__global__ __launch_bounds__(256) void k_xs(const float* __restrict__ x) {
    __shared__ float sx[32 * 49];      // [nl][bcl*12+t], pad to 49
    __shared__ float sred[8 * 32];     // [part][nl]
    __shared__ float sinv[32];
    int tid = threadIdx.x;
    int n0 = blockIdx.x * 32;
    int bcg = blockIdx.y;              // 0..3 -> bc 4*bcg .. 4*bcg+3

    // rowsum partials: part = tid>>5 (0..7), nl = tid&31 -> coalesced lines
    {
        int part = tid >> 5, nl = tid & 31;
        float s = 0.f;
#pragma unroll
        for (int q = 0; q < 8; ++q) s += g_cspart[(part * 8 + q) * NV + n0 + nl];
        sred[part * 32 + nl] = s;
    }
#pragma unroll
    for (int bcl = 0; bcl < 4; ++bcl) {
        const float* src = x + (((size_t)(bcg * 4 + bcl)) * NV + n0) * TV;
        for (int i = tid; i < 32 * TV; i += 256) {
            int nl = i / TV, t = i - nl * TV;
            sx[nl * 49 + bcl * TV + t] = src[i];
        }
    }
    __syncthreads();
    if (tid < 32) {
        float s = 0.f;
#pragma unroll
        for (int p = 0; p < 8; ++p) s += sred[p * 32 + tid];
        sinv[tid] = 4096.0f / s;
    }
    __syncthreads();
#pragma unroll
    for (int it = 0; it < 3; ++it) {
        int idx = tid + it * 256;          // 768 = 32 n x 24 local pairs
        int nl = idx / 24, rpl = idx - nl * 24;
        float inv = sinv[nl];
        __half2 hh = __floats2half2_rn(sx[nl * 49 + 2 * rpl] * inv,
                                       sx[nl * 49 + 2 * rpl + 1] * inv);
        g_Bh32[(n0 + nl) * 96 + bcg * 24 + rpl] = *(uint32_t*)&hh;
    }
}

// ========== K4: fp16 HMMA GEMM  C[m][r] = sum_n P[m][n]*xs[n][r] ==========
// grid (64, 2), 512 thr = 16 warps (2 wm x 8 wn, 24 r per warp).
#define G_BH 16384
#define G_STAGE (16384 + 25600)   /* 41984 */
#define G_SMEM (4 * G_STAGE)      /* 167936 */

__device__ __forceinline__ void g5_load(uint32_t sbase, int stage, int i0, size_t kg, int tid) {
    uint32_t S = sbase + stage * G_STAGE;
    const char* pa = (const char*)g_Ph32;
    const char* bh = (const char*)g_Bh32;
#pragma unroll
    for (int l = 0; l < 5; ++l) {
        int idx = tid + l * 512;
        if (idx < 1024) {
            int row = idx >> 3, kb = idx & 7;
            const char* src = pa + ((size_t)(i0 + row) * NV + kg + kb * 8) * 2;
            cp16(S + row * 128 + (((uint32_t)(kb ^ (row & 7))) << 4), src);
        } else if (idx < 2560) {
            int j = idx - 1024;
            int kr = j / 24, cb = j % 24;
            cp16(S + G_BH + kr * 400 + cb * 16, bh + (kg + kr) * 384 + cb * 16);
        }
    }
    asm volatile("cp.async.commit_group;" ::: "memory");
}

__global__ __launch_bounds__(512, 1) void k_gemm5() {
    extern __shared__ char sm[];
    uint32_t sbase = smem_u32(sm);
    const int tid = threadIdx.x, lane = tid & 31, wid = tid >> 5;
    const int wm = wid & 1;
    const int wn = wid >> 1;
    const int i0 = blockIdx.x * 128;
    const size_t k0 = (size_t)blockIdx.y * 4096;

    float acc[4][3][4];
#pragma unroll
    for (int mt = 0; mt < 4; ++mt)
#pragma unroll
        for (int nt = 0; nt < 3; ++nt)
#pragma unroll
            for (int q = 0; q < 4; ++q) acc[mt][nt][q] = 0.f;

    g5_load(sbase, 0, i0, k0, tid);
    g5_load(sbase, 1, i0, k0 + 64, tid);
    g5_load(sbase, 2, i0, k0 + 128, tid);

    for (int c = 0; c < 64; ++c) {
        if (c + 3 < 64) g5_load(sbase, (c + 3) & 3, i0, k0 + (size_t)(c + 3) * 64, tid);
        else asm volatile("cp.async.commit_group;" ::: "memory");
        asm volatile("cp.async.wait_group 3;" ::: "memory");
        __syncthreads();

        uint32_t A = sbase + (c & 3) * G_STAGE;
        uint32_t B = A + G_BH;
#pragma unroll
        for (int ks = 0; ks < 4; ++ks) {
            int krow = ks * 16 + (lane & 15);
            uint32_t bm[4], b4, b5;
            ldsm_x4t(bm[0], bm[1], bm[2], bm[3],
                     B + krow * 400 + (wn * 24 + (lane >> 4) * 8) * 2);
            ldsm_x2t(b4, b5, B + krow * 400 + (wn * 24 + 16) * 2);
            int kb = ks * 2 + (lane >> 4);
#pragma unroll
            for (int mt = 0; mt < 4; ++mt) {
                int rr = wm * 64 + mt * 16 + (lane & 15);
                uint32_t aa = A + rr * 128 + (((uint32_t)(kb ^ (rr & 7))) << 4);
                uint32_t a0, a1, a2, a3;
                ldsm_x4(a0, a1, a2, a3, aa);
                mma16816h(acc[mt][0], a0, a1, a2, a3, bm[0], bm[1]);
                mma16816h(acc[mt][1], a0, a1, a2, a3, bm[2], bm[3]);
                mma16816h(acc[mt][2], a0, a1, a2, a3, b4, b5);
            }
        }
        __syncthreads();
    }

    float* outp = g_part2 + (size_t)blockIdx.y * NV * RV;
#pragma unroll
    for (int mt = 0; mt < 4; ++mt) {
#pragma unroll
        for (int nt = 0; nt < 3; ++nt) {
            int m = i0 + wm * 64 + mt * 16 + (lane >> 2);
            int r = wn * 24 + nt * 8 + (lane & 3) * 2;
            *(float2*)&outp[(size_t)m * RV + r] = make_float2(acc[mt][nt][0], acc[mt][nt][1]);
            *(float2*)&outp[(size_t)(m + 8) * RV + r] = make_float2(acc[mt][nt][2], acc[mt][nt][3]);
        }
    }
}

// ========== K5: reduce 2 split-K partials (undo 4096 scale), 48B/thread ==========
__global__ __launch_bounds__(256) void k_out3(float* __restrict__ out) {
    int bid = blockIdx.x;                    // 512 = 16 bc x 32 m-blocks
    int bc = bid >> 5, mb = bid & 31;
    int m = mb * 256 + threadIdx.x;
    const float* p0 = g_part2 + (size_t)m * RV + bc * TV;
    const float* p1 = p0 + (size_t)NV * RV;
    const float sc = 1.0f / 4096.0f;
    float4 r0 = *(const float4*)p0;
    float4 r1 = *(const float4*)(p0 + 4);
    float4 r2 = *(const float4*)(p0 + 8);
    float4 s0 = *(const float4*)p1;
    float4 s1 = *(const float4*)(p1 + 4);
    float4 s2 = *(const float4*)(p1 + 8);
    r0.x = (r0.x + s0.x) * sc; r0.y = (r0.y + s0.y) * sc;
    r0.z = (r0.z + s0.z) * sc; r0.w = (r0.w + s0.w) * sc;
    r1.x = (r1.x + s1.x) * sc; r1.y = (r1.y + s1.y) * sc;
    r1.z = (r1.z + s1.z) * sc; r1.w = (r1.w + s1.w) * sc;
    r2.x = (r2.x + s2.x) * sc; r2.y = (r2.y + s2.y) * sc;
    r2.z = (r2.z + s2.z) * sc; r2.w = (r2.w + s2.w) * sc;
    float* o = out + ((size_t)bc * NV + m) * TV;
    *(float4*)o = r0;
    *(float4*)(o + 4) = r1;
    *(float4*)(o + 8) = r2;
}

extern "C" void kernel_launch(void* const* d_in, const int* in_sizes, int n_in,
                              void* d_out, int out_size) {
    const float* x    = (const float*)d_in[0];
    const float* nv1  = (const float*)d_in[1];
    const float* nv2  = (const float*)d_in[2];
    const float* tvv  = (const float*)d_in[3];
    const float* kk   = (const float*)d_in[4];
    const int*   tind = (const int*)d_in[5];
    float* out = (float*)d_out;

    cudaFuncSetAttribute(k_gemm5, cudaFuncAttributeMaxDynamicSharedMemorySize, G_SMEM);
    cudaFuncSetAttribute(k_padj_mma, cudaFuncAttributeMaxDynamicSharedMemorySize, PJ_SMEM);

    k_core<<<1, 1024>>>(tvv, kk, tind);
    k_amat<<<NV / 8, 256>>>(nv1, nv2);
    k_padj_mma<<<dim3(32, 64), 256, PJ_SMEM>>>();
    k_xs<<<dim3(NV / 32, 4), 256>>>(x);
    k_gemm5<<<dim3(64, 2), 512, G_SMEM>>>();
    k_out3<<<512, 256>>>(out);
}